// round 9
// baseline (speedup 1.0000x reference)
#include <cuda_runtime.h>
#include <cuda_bf16.h>
#include <cstdint>

// Problem constants (fixed-shape dataset)
#define D 128
#define H 256
#define MAXN 40000
#define LN_EPS 1e-5f

// Scratch: edge-message aggregation + per-receiver counts.
__device__ float g_agg[MAXN * D];
__device__ float g_cnt[MAXN];
__device__ int g_idx64;

// Pre-split, transposed weights: bf16 hi/lo planes, layout [n][k], k contiguous.
#define OFF_W1E 0
#define OFF_W1N 98304
#define OFF_W1S 163840
#define OFF_W2E 196608
#define OFF_W2N 229376
#define OFF_W2S 262144
#define WTOT    294912
__device__ __nv_bfloat16 g_whi[WTOT];
__device__ __nv_bfloat16 g_wlo[WTOT];

__device__ __forceinline__ float silu_f(float x) {
    return x / (1.0f + __expf(-x));
}

// Transpose + bf16 hi/lo split of one weight matrix src[K][N] -> planes [n][k].
__global__ void prep_kernel(const float* __restrict__ src, int dstoff, int K, int N) {
    int d = blockIdx.x * blockDim.x + threadIdx.x;
    if (d >= K * N) return;
    int n = d / K, k = d - n * K;
    float x = src[(size_t)k * N + n];
    __nv_bfloat16 h = __float2bfloat16(x);
    float r = x - __bfloat162float(h);
    g_whi[dstoff + d] = h;
    g_wlo[dstoff + d] = __float2bfloat16(r);
}

// Detect index dtype: int64 values < 2^31 have zero odd words.
__global__ void probe_kernel(const int* __restrict__ e32) {
    if (blockIdx.x == 0 && threadIdx.x == 0) {
        int all0 = 1;
#pragma unroll 1
        for (int i = 0; i < 64; ++i) {
            if (e32[2 * i + 1] != 0) { all0 = 0; break; }
        }
        g_idx64 = all0;
    }
}

__global__ void zero_kernel(int N) {
    int i = blockIdx.x * blockDim.x + threadIdx.x;
    int na = N * D;
    if (i < na) g_agg[i] = 0.0f;
    if (i < N)  g_cnt[i] = 0.0f;
}

// ---------------- mma helpers ----------------
__device__ __forceinline__ uint32_t pack_bf16x2(float lo, float hi) {
    uint32_t r;
    asm("cvt.rn.bf16x2.f32 %0, %1, %2;" : "=r"(r) : "f"(hi), "f"(lo));
    return r;
}
// Split two fp32 into bf16 hi-pair and lo-pair (residual).
__device__ __forceinline__ void split2(float2 f, uint32_t& h, uint32_t& l) {
    h = pack_bf16x2(f.x, f.y);
    float hx = __uint_as_float(h << 16);
    float hy = __uint_as_float(h & 0xffff0000u);
    l = pack_bf16x2(f.x - hx, f.y - hy);
}
__device__ __forceinline__ void mma_bf16(float c[4],
                                         uint32_t a0, uint32_t a1, uint32_t a2, uint32_t a3,
                                         uint32_t b0, uint32_t b1) {
    asm volatile(
        "mma.sync.aligned.m16n8k16.row.col.f32.bf16.bf16.f32 "
        "{%0,%1,%2,%3},{%4,%5,%6,%7},{%8,%9},{%0,%1,%2,%3};"
        : "+f"(c[0]), "+f"(c[1]), "+f"(c[2]), "+f"(c[3])
        : "r"(a0), "r"(a1), "r"(a2), "r"(a3), "r"(b0), "r"(b1));
}

// ---------------- smem layout (floats) ----------------
#define AS_STRIDE 44               // fp32 A tile stride (distinct banks for 8 rows, 16B aligned)
#define AS_BASE   0                // 32 x 44 = 1408
#define B1_BASE   1408             // 256 bias1
#define B2_BASE   1664             // 128 bias2
#define BS_BASE   1792             // bf16 planes: 2 x 10240 elems = 10240 floats
#define BS_STRIDE 40               // bf16 elems per n-row (80B; conflict-free fragment loads)
#define BS_PLANE  10240            // 256 * 40 elems
#define HS_BASE   12032            // 32 x 266 = 8512
#define HS_STRIDE 266
#define CS_STRIDE 132              // epilogue staging (reuses BS region)
#define SMEM_FLOATS 20544          // 82176 bytes

// Fused MLP+LN kernel, tensor-core (bf16 3-product split) version.
// MODE 0: edge (KTOT=384), MODE 1: node (256), MODE 2: sender (128).
// Block: 256 threads / 8 warps, 32 rows.
// GEMM1 warp tile: 16 rows x 64 cols (warp grid 2x4). GEMM2: 16 x 32 (2x4).
template <int KTOT, int MODE>
__global__ void __launch_bounds__(256, 2) mlp_kernel(
    const float* __restrict__ sx,
    const float* __restrict__ rx,
    const float* __restrict__ ea,
    const int* e32, const long long* e64,
    const float* __restrict__ b1, const float* __restrict__ b2,
    const float* __restrict__ gm, const float* __restrict__ bt,
    int w1off, int w2off,
    float* __restrict__ out,
    int M, int E)
{
    extern __shared__ float smem[];
    float* As = smem + AS_BASE;
    float* b1s = smem + B1_BASE;
    float* b2s = smem + B2_BASE;
    __nv_bfloat16* Bsh = (__nv_bfloat16*)(smem + BS_BASE);
    __nv_bfloat16* Bsl = Bsh + BS_PLANE;
    float* Hs = smem + HS_BASE;

    const int tid  = threadIdx.x;
    const int lane = tid & 31;
    const int warp = tid >> 5;
    const int row0 = blockIdx.x * 32;
    const int is64 = (MODE == 0) ? g_idx64 : 0;

    const int r0  = (warp & 1) * 16;       // warp row base (both GEMMs)
    const int n0  = (warp >> 1) * 64;      // GEMM1 col base
    const int m0  = (warp >> 1) * 32;      // GEMM2 col base
    const int g   = lane >> 2;             // group id
    const int tig = lane & 3;              // thread in group

    // stage biases
    b1s[tid] = b1[tid & 255] ;             // tid<256 always; H=256
    if (tid < 128) b2s[tid] = b2[tid];

    // ================= GEMM1: C1[32,256] = A[32,KTOT] @ W1 =================
    float c1[8][4];
#pragma unroll
    for (int j = 0; j < 8; j++)
#pragma unroll
        for (int q = 0; q < 4; q++) c1[j][q] = 0.0f;

    for (int kt = 0; kt < KTOT / 32; ++kt) {
        // ---- stage A tile fp32 [32][32] (gather) ----
        {
            int r  = tid >> 3;
            int kl = (tid & 7) * 4;
            int kg = kt * 32 + kl;
            int row = row0 + r;
            float4 v = make_float4(0.f, 0.f, 0.f, 0.f);
            if (row < M) {
                if (MODE == 0) {
                    const float* p;
                    if (kg < 128) {
                        long long s = is64 ? e64[row] : (long long)e32[row];
                        p = sx + (size_t)s * D + kg;
                    } else if (kg < 256) {
                        long long dd = is64 ? e64[E + row] : (long long)e32[E + row];
                        p = rx + (size_t)dd * D + (kg - 128);
                    } else {
                        p = ea + (size_t)row * D + (kg - 256);
                    }
                    v = *(const float4*)p;
                } else if (MODE == 1) {
                    if (kg < 128) {
                        v = *(const float4*)(rx + (size_t)row * D + kg);
                    } else {
                        float rc = 1.0f / fmaxf(g_cnt[row], 1.0f);
                        float4 t = *(const float4*)(g_agg + (size_t)row * D + (kg - 128));
                        v.x = t.x * rc; v.y = t.y * rc; v.z = t.z * rc; v.w = t.w * rc;
                    }
                } else {
                    v = *(const float4*)(sx + (size_t)row * D + kg);
                }
            }
            *(float4*)(As + r * AS_STRIDE + kl) = v;
        }
        // ---- stage W1 tile (pre-split bf16): all 256 n, 32 k ----
        {
            int n = tid;
            const uint4* sh = (const uint4*)(g_whi + w1off + (size_t)n * KTOT + kt * 32);
            const uint4* sl = (const uint4*)(g_wlo + w1off + (size_t)n * KTOT + kt * 32);
            uint4* dh = (uint4*)(Bsh + n * BS_STRIDE);
            uint4* dl = (uint4*)(Bsl + n * BS_STRIDE);
#pragma unroll
            for (int j = 0; j < 4; j++) { dh[j] = sh[j]; dl[j] = sl[j]; }
        }
        __syncthreads();

#pragma unroll
        for (int kc = 0; kc < 2; ++kc) {
            const int kb = kc * 16;
            uint32_t ah[4], al[4];
            split2(*(const float2*)(As + (r0 + g)     * AS_STRIDE + kb + tig * 2),     ah[0], al[0]);
            split2(*(const float2*)(As + (r0 + g + 8) * AS_STRIDE + kb + tig * 2),     ah[1], al[1]);
            split2(*(const float2*)(As + (r0 + g)     * AS_STRIDE + kb + tig * 2 + 8), ah[2], al[2]);
            split2(*(const float2*)(As + (r0 + g + 8) * AS_STRIDE + kb + tig * 2 + 8), ah[3], al[3]);
#pragma unroll
            for (int j = 0; j < 8; j++) {
                int nn = n0 + 8 * j + g;
                uint32_t bh0 = *(const uint32_t*)(Bsh + nn * BS_STRIDE + kb + tig * 2);
                uint32_t bh1 = *(const uint32_t*)(Bsh + nn * BS_STRIDE + kb + tig * 2 + 8);
                uint32_t bl0 = *(const uint32_t*)(Bsl + nn * BS_STRIDE + kb + tig * 2);
                uint32_t bl1 = *(const uint32_t*)(Bsl + nn * BS_STRIDE + kb + tig * 2 + 8);
                mma_bf16(c1[j], ah[0], ah[1], ah[2], ah[3], bh0, bh1);
                mma_bf16(c1[j], ah[0], ah[1], ah[2], ah[3], bl0, bl1);
                mma_bf16(c1[j], al[0], al[1], al[2], al[3], bh0, bh1);
            }
        }
        __syncthreads();
    }

    // ---- bias + SiLU -> Hs (fp32) ----
#pragma unroll
    for (int j = 0; j < 8; j++) {
        int col = n0 + 8 * j + tig * 2;
        float2 p0 = make_float2(silu_f(c1[j][0] + b1s[col]), silu_f(c1[j][1] + b1s[col + 1]));
        float2 p1 = make_float2(silu_f(c1[j][2] + b1s[col]), silu_f(c1[j][3] + b1s[col + 1]));
        *(float2*)(Hs + (r0 + g)     * HS_STRIDE + col) = p0;
        *(float2*)(Hs + (r0 + g + 8) * HS_STRIDE + col) = p1;
    }

    // ================= GEMM2: C2[32,128] = Hs[32,256] @ W2 =================
    float c2[4][4];
#pragma unroll
    for (int j = 0; j < 4; j++)
#pragma unroll
        for (int q = 0; q < 4; q++) c2[j][q] = 0.0f;

    for (int kt = 0; kt < H / 32; ++kt) {
        // stage W2 tile: 128 n, 32 k; 2 threads per n
        {
            int n = tid >> 1, half = tid & 1;
            const uint4* sh = (const uint4*)(g_whi + w2off + (size_t)n * H + kt * 32 + half * 16);
            const uint4* sl = (const uint4*)(g_wlo + w2off + (size_t)n * H + kt * 32 + half * 16);
            uint4* dh = (uint4*)(Bsh + n * BS_STRIDE + half * 16);
            uint4* dl = (uint4*)(Bsl + n * BS_STRIDE + half * 16);
            dh[0] = sh[0]; dh[1] = sh[1];
            dl[0] = sl[0]; dl[1] = sl[1];
        }
        __syncthreads();   // also orders Hs writes (all warps) before reads

#pragma unroll
        for (int kc = 0; kc < 2; ++kc) {
            const int kb  = kt * 32 + kc * 16;   // Hs k index
            const int kbl = kc * 16;             // Bs k index
            uint32_t ah[4], al[4];
            split2(*(const float2*)(Hs + (r0 + g)     * HS_STRIDE + kb + tig * 2),     ah[0], al[0]);
            split2(*(const float2*)(Hs + (r0 + g + 8) * HS_STRIDE + kb + tig * 2),     ah[1], al[1]);
            split2(*(const float2*)(Hs + (r0 + g)     * HS_STRIDE + kb + tig * 2 + 8), ah[2], al[2]);
            split2(*(const float2*)(Hs + (r0 + g + 8) * HS_STRIDE + kb + tig * 2 + 8), ah[3], al[3]);
#pragma unroll
            for (int j = 0; j < 4; j++) {
                int nn = m0 + 8 * j + g;
                uint32_t bh0 = *(const uint32_t*)(Bsh + nn * BS_STRIDE + kbl + tig * 2);
                uint32_t bh1 = *(const uint32_t*)(Bsh + nn * BS_STRIDE + kbl + tig * 2 + 8);
                uint32_t bl0 = *(const uint32_t*)(Bsl + nn * BS_STRIDE + kbl + tig * 2);
                uint32_t bl1 = *(const uint32_t*)(Bsl + nn * BS_STRIDE + kbl + tig * 2 + 8);
                mma_bf16(c2[j], ah[0], ah[1], ah[2], ah[3], bh0, bh1);
                mma_bf16(c2[j], ah[0], ah[1], ah[2], ah[3], bl0, bl1);
                mma_bf16(c2[j], al[0], al[1], al[2], al[3], bh0, bh1);
            }
        }
        __syncthreads();
    }

    // ---- stage C2 to smem (reuse Bs region), then LN epilogue ----
    float* Cs = smem + BS_BASE;
#pragma unroll
    for (int j = 0; j < 4; j++) {
        int col = m0 + 8 * j + tig * 2;
        *(float2*)(Cs + (r0 + g)     * CS_STRIDE + col) = make_float2(c2[j][0], c2[j][1]);
        *(float2*)(Cs + (r0 + g + 8) * CS_STRIDE + col) = make_float2(c2[j][2], c2[j][3]);
    }
    __syncthreads();

    // LayerNorm + residual + (edge) scatter — thread (rg,lane): rows rg*4..+3, cols lane*4..+3
    const int rg = warp;
    const int c  = lane * 4;
#pragma unroll
    for (int i = 0; i < 4; i++) {
        int grow = row0 + rg * 4 + i;   // global row (uniform per warp)
        if (grow >= M) continue;

        float4 vv = *(const float4*)(Cs + (rg * 4 + i) * CS_STRIDE + c);
        float v0 = vv.x + b2s[c + 0];
        float v1 = vv.y + b2s[c + 1];
        float v2 = vv.z + b2s[c + 2];
        float v3 = vv.w + b2s[c + 3];

        float s  = v0 + v1 + v2 + v3;
        float sq = v0 * v0 + v1 * v1 + v2 * v2 + v3 * v3;
#pragma unroll
        for (int o = 16; o > 0; o >>= 1) {
            s  += __shfl_xor_sync(0xffffffffu, s,  o);
            sq += __shfl_xor_sync(0xffffffffu, sq, o);
        }
        float mean = s * (1.0f / 128.0f);
        float var  = sq * (1.0f / 128.0f) - mean * mean;
        float rs   = rsqrtf(var + LN_EPS);

        float y0 = (v0 - mean) * rs * gm[c + 0] + bt[c + 0];
        float y1 = (v1 - mean) * rs * gm[c + 1] + bt[c + 1];
        float y2 = (v2 - mean) * rs * gm[c + 2] + bt[c + 2];
        float y3 = (v3 - mean) * rs * gm[c + 3] + bt[c + 3];

        if (MODE == 0) {
            float4 r4 = *(const float4*)(ea + (size_t)grow * D + c);
            *(float4*)(out + (size_t)grow * D + c) =
                make_float4(r4.x + y0, r4.y + y1, r4.z + y2, r4.w + y3);
            long long dn = is64 ? e64[E + grow] : (long long)e32[E + grow];
            size_t dbase = (size_t)dn * D + c;
            atomicAdd(&g_agg[dbase + 0], y0);
            atomicAdd(&g_agg[dbase + 1], y1);
            atomicAdd(&g_agg[dbase + 2], y2);
            atomicAdd(&g_agg[dbase + 3], y3);
            if (lane == 0) atomicAdd(&g_cnt[dn], 1.0f);
        } else if (MODE == 1) {
            float4 r4 = *(const float4*)(rx + (size_t)grow * D + c);
            *(float4*)(out + (size_t)grow * D + c) =
                make_float4(r4.x + y0, r4.y + y1, r4.z + y2, r4.w + y3);
        } else {
            float4 r4 = *(const float4*)(sx + (size_t)grow * D + c);
            *(float4*)(out + (size_t)grow * D + c) =
                make_float4(r4.x + y0, r4.y + y1, r4.z + y2, r4.w + y3);
        }
    }
}

extern "C" void kernel_launch(void* const* d_in, const int* in_sizes, int n_in,
                              void* d_out, int out_size)
{
    const float*     sx   = (const float*)d_in[0];
    const float*     rx   = (const float*)d_in[1];
    const float*     ea   = (const float*)d_in[2];
    const int*       e32  = (const int*)d_in[3];
    const long long* e64  = (const long long*)d_in[3];
    const float *ew1 = (const float*)d_in[4],  *eb1 = (const float*)d_in[5];
    const float *ew2 = (const float*)d_in[6],  *eb2 = (const float*)d_in[7];
    const float *eg  = (const float*)d_in[8],  *ebt = (const float*)d_in[9];
    const float *nw1 = (const float*)d_in[10], *nb1 = (const float*)d_in[11];
    const float *nw2 = (const float*)d_in[12], *nb2 = (const float*)d_in[13];
    const float *ng  = (const float*)d_in[14], *nbt = (const float*)d_in[15];
    const float *sw1 = (const float*)d_in[16], *sb1 = (const float*)d_in[17];
    const float *sw2 = (const float*)d_in[18], *sb2 = (const float*)d_in[19];
    const float *sg  = (const float*)d_in[20], *sbt = (const float*)d_in[21];

    const int N = in_sizes[0] / D;
    const int E = in_sizes[3] / 2;

    float* out          = (float*)d_out;
    float* sender_out   = out;
    float* receiver_out = out + (size_t)N * D;
    float* edge_out     = out + (size_t)2 * N * D;

    const size_t smem_bytes = (size_t)SMEM_FLOATS * sizeof(float);
    cudaFuncSetAttribute(mlp_kernel<3 * D, 0>, cudaFuncAttributeMaxDynamicSharedMemorySize, (int)smem_bytes);
    cudaFuncSetAttribute(mlp_kernel<2 * D, 1>, cudaFuncAttributeMaxDynamicSharedMemorySize, (int)smem_bytes);
    cudaFuncSetAttribute(mlp_kernel<D, 2>,     cudaFuncAttributeMaxDynamicSharedMemorySize, (int)smem_bytes);

    // 0) weight prep: transpose + bf16 hi/lo split (6 tiny launches)
    prep_kernel<<<(384 * 256 + 255) / 256, 256>>>(ew1, OFF_W1E, 384, 256);
    prep_kernel<<<(256 * 256 + 255) / 256, 256>>>(nw1, OFF_W1N, 256, 256);
    prep_kernel<<<(128 * 256 + 255) / 256, 256>>>(sw1, OFF_W1S, 128, 256);
    prep_kernel<<<(256 * 128 + 255) / 256, 256>>>(ew2, OFF_W2E, 256, 128);
    prep_kernel<<<(256 * 128 + 255) / 256, 256>>>(nw2, OFF_W2N, 256, 128);
    prep_kernel<<<(256 * 128 + 255) / 256, 256>>>(sw2, OFF_W2S, 256, 128);

    // 1) index dtype probe + scatter buffer zeroing
    probe_kernel<<<1, 32>>>(e32);
    zero_kernel<<<(N * (D + 1) + 255) / 256, 256>>>(N);

    // 2) edge MLP + residual + scatter
    mlp_kernel<3 * D, 0><<<(E + 31) / 32, 256, smem_bytes>>>(
        sx, rx, ea, e32, e64, eb1, eb2, eg, ebt, OFF_W1E, OFF_W2E, edge_out, E, E);

    // 3) node MLP + residual (consumes g_agg / g_cnt)
    mlp_kernel<2 * D, 1><<<(N + 31) / 32, 256, smem_bytes>>>(
        sx, rx, ea, e32, e64, nb1, nb2, ng, nbt, OFF_W1N, OFF_W2N, receiver_out, N, E);

    // 4) sender MLP + residual
    mlp_kernel<D, 2><<<(N + 31) / 32, 256, smem_bytes>>>(
        sx, rx, ea, e32, e64, sb1, sb2, sg, sbt, OFF_W1S, OFF_W2S, sender_out, N, E);
}

// round 12
// speedup vs baseline: 1.4966x; 1.4966x over previous
#include <cuda_runtime.h>
#include <cuda_bf16.h>
#include <cstdint>

#define D 128
#define H 256
#define MAXN 40000
#define LN_EPS 1e-5f

__device__ float g_agg[MAXN * D];
__device__ float g_cnt[MAXN];
__device__ int g_idx64;

#define OFF_W1E 0
#define OFF_W1N 98304
#define OFF_W1S 163840
#define OFF_W2E 196608
#define OFF_W2N 229376
#define OFF_W2S 262144
#define WTOT    294912
__device__ __nv_bfloat16 g_whi[WTOT];
__device__ __nv_bfloat16 g_wlo[WTOT];

__device__ __forceinline__ float silu_f(float x) { return x / (1.0f + __expf(-x)); }

__global__ void prep_kernel(const float* __restrict__ src, int dstoff, int K, int N) {
    int d = blockIdx.x * blockDim.x + threadIdx.x;
    if (d >= K * N) return;
    int n = d / K, k = d - n * K;
    float x = src[(size_t)k * N + n];
    __nv_bfloat16 h = __float2bfloat16(x);
    g_whi[dstoff + d] = h;
    g_wlo[dstoff + d] = __float2bfloat16(x - __bfloat162float(h));
}

__global__ void probe_kernel(const int* __restrict__ e32) {
    if (blockIdx.x == 0 && threadIdx.x == 0) {
        int all0 = 1;
#pragma unroll 1
        for (int i = 0; i < 64; ++i)
            if (e32[2 * i + 1] != 0) { all0 = 0; break; }
        g_idx64 = all0;
    }
}

__global__ void zero_kernel(int N) {
    int i = blockIdx.x * blockDim.x + threadIdx.x;
    if (i < N * D) g_agg[i] = 0.0f;
    if (i < N)     g_cnt[i] = 0.0f;
}

__device__ __forceinline__ uint32_t pack_bf16x2(float lo, float hi) {
    uint32_t r;
    asm("cvt.rn.bf16x2.f32 %0, %1, %2;" : "=r"(r) : "f"(hi), "f"(lo));
    return r;
}
__device__ __forceinline__ void split2(float2 f, uint32_t& h, uint32_t& l) {
    h = pack_bf16x2(f.x, f.y);
    float hx = __uint_as_float(h << 16);
    float hy = __uint_as_float(h & 0xffff0000u);
    l = pack_bf16x2(f.x - hx, f.y - hy);
}
__device__ __forceinline__ void mma_bf16(float c[4],
                                         uint32_t a0, uint32_t a1, uint32_t a2, uint32_t a3,
                                         uint32_t b0, uint32_t b1) {
    asm volatile(
        "mma.sync.aligned.m16n8k16.row.col.f32.bf16.bf16.f32 "
        "{%0,%1,%2,%3},{%4,%5,%6,%7},{%8,%9},{%0,%1,%2,%3};"
        : "+f"(c[0]), "+f"(c[1]), "+f"(c[2]), "+f"(c[3])
        : "r"(a0), "r"(a1), "r"(a2), "r"(a3), "r"(b0), "r"(b1));
}
#define LDSM_X4(r0_, r1_, r2_, r3_, addr) \
    asm volatile("ldmatrix.sync.aligned.m8n8.x4.shared.b16 {%0,%1,%2,%3}, [%4];" \
        : "=r"(r0_), "=r"(r1_), "=r"(r2_), "=r"(r3_) : "r"(addr))

// smem byte map:
//  0      b1s  float[256]
//  1024   b2s  float[128]
//  1536   Ah   [32 rows][40 bf16]  (stride 80B)   2560B
//  4096   Al                                       2560B
//  6656   Bsh  [256 n][40 bf16]   (stride 80B)   20480B   (Cs fp32 reuses this)
//  27136  Bsl                                    20480B
//  47616  Hh   [32 rows][264 bf16](stride 528B)  16896B
//  64512  Hl                                     16896B
#define SM_B1S 0
#define SM_B2S 1024
#define SM_AH  1536
#define SM_AL  4096
#define SM_BSH 6656
#define SM_BSL 27136
#define SM_HH  47616
#define SM_HL  64512
#define SMEM_BYTES 81408
#define CS_STRIDE 132

// mma.sync bf16 3-product fused MLP+LN. 256 threads / 8 warps, 32 rows/CTA.
// GEMM1 warp tile 16x64 (grid 2x4); GEMM2 16x32.
template <int KTOT, int MODE>
__global__ void __launch_bounds__(256, 2) mlp_kernel(
    const float* __restrict__ sx, const float* __restrict__ rx,
    const float* __restrict__ ea,
    const int* e32, const long long* e64,
    const float* __restrict__ b1, const float* __restrict__ b2,
    const float* __restrict__ gm, const float* __restrict__ bt,
    int w1off, int w2off, float* __restrict__ out, int M, int E)
{
    extern __shared__ char smem[];
    const uint32_t sbase = (uint32_t)__cvta_generic_to_shared(smem);
    float* b1s = (float*)(smem + SM_B1S);
    float* b2s = (float*)(smem + SM_B2S);

    const int tid  = threadIdx.x;
    const int lane = tid & 31;
    const int warp = tid >> 5;
    const int row0 = blockIdx.x * 32;
    const int is64 = (MODE == 0) ? g_idx64 : 0;

    const int r0  = (warp & 1) * 16;
    const int n0  = (warp >> 1) * 64;
    const int m0  = (warp >> 1) * 32;
    const int g   = lane >> 2;
    const int tig = lane & 3;

    b1s[tid] = b1[tid];
    if (tid < 128) b2s[tid] = b2[tid];

    // ldmatrix per-lane address components
    const int aRow = r0 + (lane & 7) + ((lane >> 3) & 1) * 8;  // A/H row
    const int aK8  = ((lane >> 4) & 1) * 8;                    // A/H k sub-tile
    const int bN   = (lane & 7) + ((lane >> 4) & 1) * 8;       // B n within 16
    const int bK8  = ((lane >> 3) & 1) * 8;                    // B k sub-tile
    const uint32_t addrA  = sbase + SM_AH + aRow * 80 + aK8 * 2;
    const uint32_t addrH  = sbase + SM_HH + aRow * 528 + aK8 * 2;
    const uint32_t addrB1 = sbase + SM_BSH + (n0 + bN) * 80 + bK8 * 2;
    const uint32_t addrB2 = sbase + SM_BSH + (m0 + bN) * 80 + bK8 * 2;

    float c1[8][4];
#pragma unroll
    for (int j = 0; j < 8; j++)
#pragma unroll
        for (int q = 0; q < 4; q++) c1[j][q] = 0.0f;

    // ================= GEMM1 =================
    for (int kt = 0; kt < KTOT / 32; ++kt) {
        const int ktb = kt * 32;
        {   // stage A: gather fp32 -> bf16 hi/lo planes
            int r  = tid >> 3;
            int kl = (tid & 7) * 4;
            int kg = ktb + kl;
            int row = row0 + r;
            float4 v = make_float4(0.f, 0.f, 0.f, 0.f);
            if (row < M) {
                if (MODE == 0) {
                    const float* p;
                    if (kg < 128) {
                        long long s = is64 ? e64[row] : (long long)e32[row];
                        p = sx + (size_t)s * D + kg;
                    } else if (kg < 256) {
                        long long dd = is64 ? e64[E + row] : (long long)e32[E + row];
                        p = rx + (size_t)dd * D + (kg - 128);
                    } else {
                        p = ea + (size_t)row * D + (kg - 256);
                    }
                    v = *(const float4*)p;
                } else if (MODE == 1) {
                    if (kg < 128) {
                        v = *(const float4*)(rx + (size_t)row * D + kg);
                    } else {
                        float rc = 1.0f / fmaxf(g_cnt[row], 1.0f);
                        float4 t = *(const float4*)(g_agg + (size_t)row * D + (kg - 128));
                        v.x = t.x * rc; v.y = t.y * rc; v.z = t.z * rc; v.w = t.w * rc;
                    }
                } else {
                    v = *(const float4*)(sx + (size_t)row * D + kg);
                }
            }
            uint32_t h0, h1, l0, l1;
            split2(make_float2(v.x, v.y), h0, l0);
            split2(make_float2(v.z, v.w), h1, l1);
            *(uint2*)(smem + SM_AH + r * 80 + kl * 2) = make_uint2(h0, h1);
            *(uint2*)(smem + SM_AL + r * 80 + kl * 2) = make_uint2(l0, l1);
        }
        // stage W1 tile: 256n x 32k, hi/lo
#pragma unroll
        for (int i = 0; i < 4; i++) {
            int idx = tid + i * 256;
            int n = idx >> 2, q = idx & 3;
            const char* sh = (const char*)(g_whi + w1off + (size_t)n * KTOT + ktb);
            const char* sl = (const char*)(g_wlo + w1off + (size_t)n * KTOT + ktb);
            *(uint4*)(smem + SM_BSH + n * 80 + q * 16) = *(const uint4*)(sh + q * 16);
            *(uint4*)(smem + SM_BSL + n * 80 + q * 16) = *(const uint4*)(sl + q * 16);
        }
        __syncthreads();

#pragma unroll
        for (int kc = 0; kc < 2; ++kc) {
            const int kb2 = kc * 32;   // k byte offset (16 elems * 2B)
            uint32_t ah[4], al[4];
            LDSM_X4(ah[0], ah[1], ah[2], ah[3], addrA + kb2);
            LDSM_X4(al[0], al[1], al[2], al[3], addrA + 2560 + kb2);
#pragma unroll
            for (int jj = 0; jj < 4; ++jj) {
                uint32_t ba = addrB1 + jj * 1280 + kb2;
                uint32_t bh0, bh1, bh2, bh3, bl0, bl1, bl2, bl3;
                LDSM_X4(bh0, bh1, bh2, bh3, ba);
                LDSM_X4(bl0, bl1, bl2, bl3, ba + 20480);
                mma_bf16(c1[2 * jj],     ah[0], ah[1], ah[2], ah[3], bh0, bh1);
                mma_bf16(c1[2 * jj],     ah[0], ah[1], ah[2], ah[3], bl0, bl1);
                mma_bf16(c1[2 * jj],     al[0], al[1], al[2], al[3], bh0, bh1);
                mma_bf16(c1[2 * jj + 1], ah[0], ah[1], ah[2], ah[3], bh2, bh3);
                mma_bf16(c1[2 * jj + 1], ah[0], ah[1], ah[2], ah[3], bl2, bl3);
                mma_bf16(c1[2 * jj + 1], al[0], al[1], al[2], al[3], bh2, bh3);
            }
        }
        __syncthreads();
    }

    // ---- bias + SiLU -> H bf16 hi/lo planes ----
#pragma unroll
    for (int j = 0; j < 8; j++) {
        int col = n0 + 8 * j + tig * 2;
        float x0 = silu_f(c1[j][0] + b1s[col]);
        float x1 = silu_f(c1[j][1] + b1s[col + 1]);
        float x2 = silu_f(c1[j][2] + b1s[col]);
        float x3 = silu_f(c1[j][3] + b1s[col + 1]);
        uint32_t h, l;
        split2(make_float2(x0, x1), h, l);
        *(uint32_t*)(smem + SM_HH + (r0 + g) * 528 + col * 2) = h;
        *(uint32_t*)(smem + SM_HL + (r0 + g) * 528 + col * 2) = l;
        split2(make_float2(x2, x3), h, l);
        *(uint32_t*)(smem + SM_HH + (r0 + g + 8) * 528 + col * 2) = h;
        *(uint32_t*)(smem + SM_HL + (r0 + g + 8) * 528 + col * 2) = l;
    }
    __syncthreads();

    // ================= GEMM2 =================
    float c2[4][4];
#pragma unroll
    for (int j = 0; j < 4; j++)
#pragma unroll
        for (int q = 0; q < 4; q++) c2[j][q] = 0.0f;

    for (int kt = 0; kt < H / 32; ++kt) {
        const int ktb = kt * 32;
        // stage W2 tile: 128n x 32k hi/lo
#pragma unroll
        for (int i = 0; i < 2; i++) {
            int idx = tid + i * 256;
            int n = idx >> 2, q = idx & 3;
            const char* sh = (const char*)(g_whi + w2off + (size_t)n * H + ktb);
            const char* sl = (const char*)(g_wlo + w2off + (size_t)n * H + ktb);
            *(uint4*)(smem + SM_BSH + n * 80 + q * 16) = *(const uint4*)(sh + q * 16);
            *(uint4*)(smem + SM_BSL + n * 80 + q * 16) = *(const uint4*)(sl + q * 16);
        }
        __syncthreads();

#pragma unroll
        for (int kc = 0; kc < 2; ++kc) {
            const int kb2 = kc * 32;
            uint32_t ah[4], al[4];
            LDSM_X4(ah[0], ah[1], ah[2], ah[3], addrH + ktb * 2 + kb2);
            LDSM_X4(al[0], al[1], al[2], al[3], addrH + 16896 + ktb * 2 + kb2);
#pragma unroll
            for (int jj = 0; jj < 2; ++jj) {
                uint32_t ba = addrB2 + jj * 1280 + kb2;
                uint32_t bh0, bh1, bh2, bh3, bl0, bl1, bl2, bl3;
                LDSM_X4(bh0, bh1, bh2, bh3, ba);
                LDSM_X4(bl0, bl1, bl2, bl3, ba + 20480);
                mma_bf16(c2[2 * jj],     ah[0], ah[1], ah[2], ah[3], bh0, bh1);
                mma_bf16(c2[2 * jj],     ah[0], ah[1], ah[2], ah[3], bl0, bl1);
                mma_bf16(c2[2 * jj],     al[0], al[1], al[2], al[3], bh0, bh1);
                mma_bf16(c2[2 * jj + 1], ah[0], ah[1], ah[2], ah[3], bh2, bh3);
                mma_bf16(c2[2 * jj + 1], ah[0], ah[1], ah[2], ah[3], bl2, bl3);
                mma_bf16(c2[2 * jj + 1], al[0], al[1], al[2], al[3], bh2, bh3);
            }
        }
        __syncthreads();
    }

    // ---- stage C2 (reuse B region as fp32), LN epilogue ----
    float* Cs = (float*)(smem + SM_BSH);
#pragma unroll
    for (int j = 0; j < 4; j++) {
        int col = m0 + 8 * j + tig * 2;
        *(float2*)(Cs + (r0 + g)     * CS_STRIDE + col) = make_float2(c2[j][0], c2[j][1]);
        *(float2*)(Cs + (r0 + g + 8) * CS_STRIDE + col) = make_float2(c2[j][2], c2[j][3]);
    }
    __syncthreads();

    const int rg = warp;
    const int c  = lane * 4;
#pragma unroll
    for (int i = 0; i < 4; i++) {
        int grow = row0 + rg * 4 + i;
        if (grow >= M) continue;

        float4 vv = *(const float4*)(Cs + (rg * 4 + i) * CS_STRIDE + c);
        float v0 = vv.x + b2s[c + 0];
        float v1 = vv.y + b2s[c + 1];
        float v2 = vv.z + b2s[c + 2];
        float v3 = vv.w + b2s[c + 3];

        float s  = v0 + v1 + v2 + v3;
        float sq = v0 * v0 + v1 * v1 + v2 * v2 + v3 * v3;
#pragma unroll
        for (int o = 16; o > 0; o >>= 1) {
            s  += __shfl_xor_sync(0xffffffffu, s,  o);
            sq += __shfl_xor_sync(0xffffffffu, sq, o);
        }
        float mean = s * (1.0f / 128.0f);
        float var  = sq * (1.0f / 128.0f) - mean * mean;
        float rs   = rsqrtf(var + LN_EPS);

        float y0 = (v0 - mean) * rs * gm[c + 0] + bt[c + 0];
        float y1 = (v1 - mean) * rs * gm[c + 1] + bt[c + 1];
        float y2 = (v2 - mean) * rs * gm[c + 2] + bt[c + 2];
        float y3 = (v3 - mean) * rs * gm[c + 3] + bt[c + 3];

        if (MODE == 0) {
            float4 r4 = *(const float4*)(ea + (size_t)grow * D + c);
            *(float4*)(out + (size_t)grow * D + c) =
                make_float4(r4.x + y0, r4.y + y1, r4.z + y2, r4.w + y3);
            long long dn = is64 ? e64[E + grow] : (long long)e32[E + grow];
            size_t dbase = (size_t)dn * D + c;
            atomicAdd(&g_agg[dbase + 0], y0);
            atomicAdd(&g_agg[dbase + 1], y1);
            atomicAdd(&g_agg[dbase + 2], y2);
            atomicAdd(&g_agg[dbase + 3], y3);
            if (lane == 0) atomicAdd(&g_cnt[dn], 1.0f);
        } else if (MODE == 1) {
            float4 r4 = *(const float4*)(rx + (size_t)grow * D + c);
            *(float4*)(out + (size_t)grow * D + c) =
                make_float4(r4.x + y0, r4.y + y1, r4.z + y2, r4.w + y3);
        } else {
            float4 r4 = *(const float4*)(sx + (size_t)grow * D + c);
            *(float4*)(out + (size_t)grow * D + c) =
                make_float4(r4.x + y0, r4.y + y1, r4.z + y2, r4.w + y3);
        }
    }
}

extern "C" void kernel_launch(void* const* d_in, const int* in_sizes, int n_in,
                              void* d_out, int out_size)
{
    const float*     sx   = (const float*)d_in[0];
    const float*     rx   = (const float*)d_in[1];
    const float*     ea   = (const float*)d_in[2];
    const int*       e32  = (const int*)d_in[3];
    const long long* e64  = (const long long*)d_in[3];
    const float *ew1 = (const float*)d_in[4],  *eb1 = (const float*)d_in[5];
    const float *ew2 = (const float*)d_in[6],  *eb2 = (const float*)d_in[7];
    const float *eg  = (const float*)d_in[8],  *ebt = (const float*)d_in[9];
    const float *nw1 = (const float*)d_in[10], *nb1 = (const float*)d_in[11];
    const float *nw2 = (const float*)d_in[12], *nb2 = (const float*)d_in[13];
    const float *ng  = (const float*)d_in[14], *nbt = (const float*)d_in[15];
    const float *sw1 = (const float*)d_in[16], *sb1 = (const float*)d_in[17];
    const float *sw2 = (const float*)d_in[18], *sb2 = (const float*)d_in[19];
    const float *sg  = (const float*)d_in[20], *sbt = (const float*)d_in[21];

    const int N = in_sizes[0] / D;
    const int E = in_sizes[3] / 2;

    float* out          = (float*)d_out;
    float* sender_out   = out;
    float* receiver_out = out + (size_t)N * D;
    float* edge_out     = out + (size_t)2 * N * D;

    cudaFuncSetAttribute(mlp_kernel<3 * D, 0>, cudaFuncAttributeMaxDynamicSharedMemorySize, SMEM_BYTES);
    cudaFuncSetAttribute(mlp_kernel<2 * D, 1>, cudaFuncAttributeMaxDynamicSharedMemorySize, SMEM_BYTES);
    cudaFuncSetAttribute(mlp_kernel<D, 2>,     cudaFuncAttributeMaxDynamicSharedMemorySize, SMEM_BYTES);

    prep_kernel<<<(384 * 256 + 255) / 256, 256>>>(ew1, OFF_W1E, 384, 256);
    prep_kernel<<<(256 * 256 + 255) / 256, 256>>>(nw1, OFF_W1N, 256, 256);
    prep_kernel<<<(128 * 256 + 255) / 256, 256>>>(sw1, OFF_W1S, 128, 256);
    prep_kernel<<<(256 * 128 + 255) / 256, 256>>>(ew2, OFF_W2E, 256, 128);
    prep_kernel<<<(256 * 128 + 255) / 256, 256>>>(nw2, OFF_W2N, 256, 128);
    prep_kernel<<<(256 * 128 + 255) / 256, 256>>>(sw2, OFF_W2S, 256, 128);

    probe_kernel<<<1, 32>>>(e32);
    zero_kernel<<<(N * (D + 1) + 255) / 256, 256>>>(N);

    mlp_kernel<3 * D, 0><<<(E + 31) / 32, 256, SMEM_BYTES>>>(
        sx, rx, ea, e32, e64, eb1, eb2, eg, ebt, OFF_W1E, OFF_W2E, edge_out, E, E);

    mlp_kernel<2 * D, 1><<<(N + 31) / 32, 256, SMEM_BYTES>>>(
        sx, rx, ea, e32, e64, nb1, nb2, ng, nbt, OFF_W1N, OFF_W2N, receiver_out, N, E);

    mlp_kernel<D, 2><<<(N + 31) / 32, 256, SMEM_BYTES>>>(
        sx, rx, ea, e32, e64, sb1, sb2, sg, sbt, OFF_W1S, OFF_W2S, sender_out, N, E);
}

// round 13
// speedup vs baseline: 1.7426x; 1.1643x over previous
#include <cuda_runtime.h>
#include <cuda_bf16.h>
#include <cstdint>

#define D 128
#define H 256
#define MAXN 40000
#define LN_EPS 1e-5f

__device__ float g_agg[MAXN * D];
__device__ float g_cnt[MAXN];
__device__ int g_idx64;

#define OFF_W1E 0
#define OFF_W1N 98304
#define OFF_W1S 163840
#define OFF_W2E 196608
#define OFF_W2N 229376
#define OFF_W2S 262144
#define WTOT    294912
__device__ __nv_bfloat16 g_whi[WTOT];
__device__ __nv_bfloat16 g_wlo[WTOT];

__device__ __forceinline__ float silu_f(float x) { return x / (1.0f + __expf(-x)); }

__global__ void prep_kernel(const float* __restrict__ src, int dstoff, int K, int N) {
    int d = blockIdx.x * blockDim.x + threadIdx.x;
    if (d >= K * N) return;
    int n = d / K, k = d - n * K;
    float x = src[(size_t)k * N + n];
    __nv_bfloat16 h = __float2bfloat16(x);
    g_whi[dstoff + d] = h;
    g_wlo[dstoff + d] = __float2bfloat16(x - __bfloat162float(h));
}

__global__ void probe_kernel(const int* __restrict__ e32) {
    if (blockIdx.x == 0 && threadIdx.x == 0) {
        int all0 = 1;
#pragma unroll 1
        for (int i = 0; i < 64; ++i)
            if (e32[2 * i + 1] != 0) { all0 = 0; break; }
        g_idx64 = all0;
    }
}

__global__ void zero_kernel(int N) {
    int i = blockIdx.x * blockDim.x + threadIdx.x;
    if (i < N * D) g_agg[i] = 0.0f;
    if (i < N)     g_cnt[i] = 0.0f;
}

__device__ __forceinline__ uint32_t pack_bf16x2(float lo, float hi) {
    uint32_t r;
    asm("cvt.rn.bf16x2.f32 %0, %1, %2;" : "=r"(r) : "f"(hi), "f"(lo));
    return r;
}
__device__ __forceinline__ void split2(float2 f, uint32_t& h, uint32_t& l) {
    h = pack_bf16x2(f.x, f.y);
    float hx = __uint_as_float(h << 16);
    float hy = __uint_as_float(h & 0xffff0000u);
    l = pack_bf16x2(f.x - hx, f.y - hy);
}
__device__ __forceinline__ void mma_bf16(float c[4],
                                         uint32_t a0, uint32_t a1, uint32_t a2, uint32_t a3,
                                         uint32_t b0, uint32_t b1) {
    asm volatile(
        "mma.sync.aligned.m16n8k16.row.col.f32.bf16.bf16.f32 "
        "{%0,%1,%2,%3},{%4,%5,%6,%7},{%8,%9},{%0,%1,%2,%3};"
        : "+f"(c[0]), "+f"(c[1]), "+f"(c[2]), "+f"(c[3])
        : "r"(a0), "r"(a1), "r"(a2), "r"(a3), "r"(b0), "r"(b1));
}
#define LDSM_X4(r0_, r1_, r2_, r3_, addr) \
    asm volatile("ldmatrix.sync.aligned.m8n8.x4.shared.b16 {%0,%1,%2,%3}, [%4];" \
        : "=r"(r0_), "=r"(r1_), "=r"(r2_), "=r"(r3_) : "r"(addr))
#define CP16(dst, src) \
    asm volatile("cp.async.ca.shared.global [%0], [%1], 16;" :: "r"(dst), "l"(src))
#define CP_COMMIT() asm volatile("cp.async.commit_group;")
#define CP_WAIT0()  asm volatile("cp.async.wait_group 0;" ::: "memory")
#define CP_WAIT1()  asm volatile("cp.async.wait_group 1;" ::: "memory")

// smem byte map (64 rows/CTA):
//  0       b1s float[256]
//  1024    b2s float[128]
//  1536    Ah [64][40bf16] s80   5120
//  6656    Al                    5120
//  11776   B buffers: buf b at +b*40960; plane hi +0, lo +20480 (256n x s80)
//  93696   Hh [64][264bf16] s528 33792
//  127488  Hl                    33792
#define SM_B1S 0
#define SM_B2S 1024
#define SM_AH  1536
#define SM_AL  6656
#define SM_BS  11776
#define SM_HH  93696
#define SM_HL  127488
#define SMEM_BYTES 161280
#define CS_STRIDE 132

// mma.sync bf16 3-product fused MLP+LN. 512 threads / 16 warps (4 row x 4 col),
// 64 rows/CTA, double-buffered cp.async B staging.
template <int KTOT, int MODE>
__global__ void __launch_bounds__(512, 1) mlp_kernel(
    const float* __restrict__ sx, const float* __restrict__ rx,
    const float* __restrict__ ea,
    const int* e32, const long long* e64,
    const float* __restrict__ b1, const float* __restrict__ b2,
    const float* __restrict__ gm, const float* __restrict__ bt,
    int w1off, int w2off, float* __restrict__ out, int M, int E)
{
    extern __shared__ char smem[];
    const uint32_t sbase = (uint32_t)__cvta_generic_to_shared(smem);
    float* b1s = (float*)(smem + SM_B1S);
    float* b2s = (float*)(smem + SM_B2S);

    const int tid  = threadIdx.x;
    const int lane = tid & 31;
    const int warp = tid >> 5;
    const int row0 = blockIdx.x * 64;
    const int is64 = (MODE == 0) ? g_idx64 : 0;

    const int r0  = (warp & 3) * 16;       // row-warp base (4 groups x 16)
    const int n0  = (warp >> 2) * 64;      // GEMM1 col base (4 groups x 64)
    const int m0  = (warp >> 2) * 32;      // GEMM2 col base
    const int g   = lane >> 2;
    const int tig = lane & 3;

    if (tid < 256) b1s[tid] = b1[tid];
    else if (tid < 384) b2s[tid - 256] = b2[tid - 256];

    const int aRow = r0 + (lane & 7) + ((lane >> 3) & 1) * 8;
    const int aK8  = ((lane >> 4) & 1) * 8;
    const int bN   = (lane & 7) + ((lane >> 4) & 1) * 8;
    const int bK8  = ((lane >> 3) & 1) * 8;
    const uint32_t addrA  = sbase + SM_AH + aRow * 80 + aK8 * 2;
    const uint32_t addrH  = sbase + SM_HH + aRow * 528 + aK8 * 2;
    const uint32_t addrB1 = sbase + SM_BS + (n0 + bN) * 80 + bK8 * 2;
    const uint32_t addrB2 = sbase + SM_BS + (m0 + bN) * 80 + bK8 * 2;

    // cp.async staging of one W1 k-tile (256n x 32k, hi+lo) into buffer bsel.
    auto stageB1 = [&](int kt, int bsel) {
        const int ktb = kt * 32;
        const uint32_t db = sbase + SM_BS + bsel * 40960;
#pragma unroll
        for (int i = 0; i < 2; i++) {
            int idx = tid + i * 512;              // 1024 chunks per plane
            int n = idx >> 2, q = idx & 3;
            uint32_t dst = db + n * 80 + q * 16;
            CP16(dst,         (const char*)(g_whi + w1off + (size_t)n * KTOT + ktb) + q * 16);
            CP16(dst + 20480, (const char*)(g_wlo + w1off + (size_t)n * KTOT + ktb) + q * 16);
        }
    };
    // W2 k-tile (128n x 32k, hi+lo)
    auto stageB2 = [&](int kt, int bsel) {
        const int ktb = kt * 32;
        const uint32_t db = sbase + SM_BS + bsel * 40960;
        int n = tid >> 2, q = tid & 3;            // 512 chunks per plane
        uint32_t dst = db + n * 80 + q * 16;
        CP16(dst,         (const char*)(g_whi + w2off + (size_t)n * H + ktb) + q * 16);
        CP16(dst + 20480, (const char*)(g_wlo + w2off + (size_t)n * H + ktb) + q * 16);
    };

    float c1[8][4];
#pragma unroll
    for (int j = 0; j < 8; j++)
#pragma unroll
        for (int q = 0; q < 4; q++) c1[j][q] = 0.0f;

    // ================= GEMM1 =================
    const int NT1 = KTOT / 32;
    stageB1(0, 0);
    CP_COMMIT();

    for (int kt = 0; kt < NT1; ++kt) {
        const int ktb = kt * 32;
        {   // stage A tile (64 rows x 32 k): 1 float4/thread, split to hi/lo planes
            int r  = tid >> 3;
            int kl = (tid & 7) * 4;
            int kg = ktb + kl;
            int row = row0 + r;
            float4 v = make_float4(0.f, 0.f, 0.f, 0.f);
            if (row < M) {
                if (MODE == 0) {
                    const float* p;
                    if (kg < 128) {
                        long long s = is64 ? e64[row] : (long long)e32[row];
                        p = sx + (size_t)s * D + kg;
                    } else if (kg < 256) {
                        long long dd = is64 ? e64[E + row] : (long long)e32[E + row];
                        p = rx + (size_t)dd * D + (kg - 128);
                    } else {
                        p = ea + (size_t)row * D + (kg - 256);
                    }
                    v = *(const float4*)p;
                } else if (MODE == 1) {
                    if (kg < 128) {
                        v = *(const float4*)(rx + (size_t)row * D + kg);
                    } else {
                        float rc = 1.0f / fmaxf(g_cnt[row], 1.0f);
                        float4 t = *(const float4*)(g_agg + (size_t)row * D + (kg - 128));
                        v.x = t.x * rc; v.y = t.y * rc; v.z = t.z * rc; v.w = t.w * rc;
                    }
                } else {
                    v = *(const float4*)(sx + (size_t)row * D + kg);
                }
            }
            uint32_t h0, h1, l0, l1;
            split2(make_float2(v.x, v.y), h0, l0);
            split2(make_float2(v.z, v.w), h1, l1);
            *(uint2*)(smem + SM_AH + r * 80 + kl * 2) = make_uint2(h0, h1);
            *(uint2*)(smem + SM_AL + r * 80 + kl * 2) = make_uint2(l0, l1);
        }
        if (kt + 1 < NT1) { stageB1(kt + 1, (kt + 1) & 1); CP_COMMIT(); CP_WAIT1(); }
        else              { CP_WAIT0(); }
        __syncthreads();

        const uint32_t bb = addrB1 + (kt & 1) * 40960;
#pragma unroll
        for (int kc = 0; kc < 2; ++kc) {
            const int kb2 = kc * 32;
            uint32_t ah[4], al[4];
            LDSM_X4(ah[0], ah[1], ah[2], ah[3], addrA + kb2);
            LDSM_X4(al[0], al[1], al[2], al[3], addrA + 5120 + kb2);
#pragma unroll
            for (int jj = 0; jj < 4; ++jj) {
                uint32_t ba = bb + jj * 1280 + kb2;
                uint32_t bh0, bh1, bh2, bh3, bl0, bl1, bl2, bl3;
                LDSM_X4(bh0, bh1, bh2, bh3, ba);
                LDSM_X4(bl0, bl1, bl2, bl3, ba + 20480);
                mma_bf16(c1[2 * jj],     ah[0], ah[1], ah[2], ah[3], bh0, bh1);
                mma_bf16(c1[2 * jj],     ah[0], ah[1], ah[2], ah[3], bl0, bl1);
                mma_bf16(c1[2 * jj],     al[0], al[1], al[2], al[3], bh0, bh1);
                mma_bf16(c1[2 * jj + 1], ah[0], ah[1], ah[2], ah[3], bh2, bh3);
                mma_bf16(c1[2 * jj + 1], ah[0], ah[1], ah[2], ah[3], bl2, bl3);
                mma_bf16(c1[2 * jj + 1], al[0], al[1], al[2], al[3], bh2, bh3);
            }
        }
        __syncthreads();
    }

    // prefetch GEMM2 tile 0 under the SiLU phase
    stageB2(0, 0);
    CP_COMMIT();

    // ---- bias + SiLU -> H bf16 hi/lo planes ----
#pragma unroll
    for (int j = 0; j < 8; j++) {
        int col = n0 + 8 * j + tig * 2;
        float x0 = silu_f(c1[j][0] + b1s[col]);
        float x1 = silu_f(c1[j][1] + b1s[col + 1]);
        float x2 = silu_f(c1[j][2] + b1s[col]);
        float x3 = silu_f(c1[j][3] + b1s[col + 1]);
        uint32_t h, l;
        split2(make_float2(x0, x1), h, l);
        *(uint32_t*)(smem + SM_HH + (r0 + g) * 528 + col * 2) = h;
        *(uint32_t*)(smem + SM_HL + (r0 + g) * 528 + col * 2) = l;
        split2(make_float2(x2, x3), h, l);
        *(uint32_t*)(smem + SM_HH + (r0 + g + 8) * 528 + col * 2) = h;
        *(uint32_t*)(smem + SM_HL + (r0 + g + 8) * 528 + col * 2) = l;
    }

    // ================= GEMM2 =================
    float c2[4][4];
#pragma unroll
    for (int j = 0; j < 4; j++)
#pragma unroll
        for (int q = 0; q < 4; q++) c2[j][q] = 0.0f;

    const int NT2 = H / 32;
    for (int kt = 0; kt < NT2; ++kt) {
        if (kt + 1 < NT2) { stageB2(kt + 1, (kt + 1) & 1); CP_COMMIT(); CP_WAIT1(); }
        else              { CP_WAIT0(); }
        __syncthreads();   // also orders H writes before LDSM reads (first iter)

        const uint32_t bb = addrB2 + (kt & 1) * 40960;
        const int ktb = kt * 32;
#pragma unroll
        for (int kc = 0; kc < 2; ++kc) {
            const int kb2 = kc * 32;
            uint32_t ah[4], al[4];
            LDSM_X4(ah[0], ah[1], ah[2], ah[3], addrH + ktb * 2 + kb2);
            LDSM_X4(al[0], al[1], al[2], al[3], addrH + 33792 + ktb * 2 + kb2);
#pragma unroll
            for (int jj = 0; jj < 2; ++jj) {
                uint32_t ba = bb + jj * 1280 + kb2;
                uint32_t bh0, bh1, bh2, bh3, bl0, bl1, bl2, bl3;
                LDSM_X4(bh0, bh1, bh2, bh3, ba);
                LDSM_X4(bl0, bl1, bl2, bl3, ba + 20480);
                mma_bf16(c2[2 * jj],     ah[0], ah[1], ah[2], ah[3], bh0, bh1);
                mma_bf16(c2[2 * jj],     ah[0], ah[1], ah[2], ah[3], bl0, bl1);
                mma_bf16(c2[2 * jj],     al[0], al[1], al[2], al[3], bh0, bh1);
                mma_bf16(c2[2 * jj + 1], ah[0], ah[1], ah[2], ah[3], bh2, bh3);
                mma_bf16(c2[2 * jj + 1], ah[0], ah[1], ah[2], ah[3], bl2, bl3);
                mma_bf16(c2[2 * jj + 1], al[0], al[1], al[2], al[3], bh2, bh3);
            }
        }
        __syncthreads();
    }

    // ---- stage C2 (fp32, reuse B region), LN epilogue ----
    float* Cs = (float*)(smem + SM_BS);
#pragma unroll
    for (int j = 0; j < 4; j++) {
        int col = m0 + 8 * j + tig * 2;
        *(float2*)(Cs + (r0 + g)     * CS_STRIDE + col) = make_float2(c2[j][0], c2[j][1]);
        *(float2*)(Cs + (r0 + g + 8) * CS_STRIDE + col) = make_float2(c2[j][2], c2[j][3]);
    }
    __syncthreads();

    const int c = lane * 4;
#pragma unroll
    for (int i = 0; i < 4; i++) {
        int lrow = warp * 4 + i;
        int grow = row0 + lrow;
        if (grow >= M) continue;

        float4 vv = *(const float4*)(Cs + lrow * CS_STRIDE + c);
        float v0 = vv.x + b2s[c + 0];
        float v1 = vv.y + b2s[c + 1];
        float v2 = vv.z + b2s[c + 2];
        float v3 = vv.w + b2s[c + 3];

        float s  = v0 + v1 + v2 + v3;
        float sq = v0 * v0 + v1 * v1 + v2 * v2 + v3 * v3;
#pragma unroll
        for (int o = 16; o > 0; o >>= 1) {
            s  += __shfl_xor_sync(0xffffffffu, s,  o);
            sq += __shfl_xor_sync(0xffffffffu, sq, o);
        }
        float mean = s * (1.0f / 128.0f);
        float var  = sq * (1.0f / 128.0f) - mean * mean;
        float rs   = rsqrtf(var + LN_EPS);

        float y0 = (v0 - mean) * rs * gm[c + 0] + bt[c + 0];
        float y1 = (v1 - mean) * rs * gm[c + 1] + bt[c + 1];
        float y2 = (v2 - mean) * rs * gm[c + 2] + bt[c + 2];
        float y3 = (v3 - mean) * rs * gm[c + 3] + bt[c + 3];

        if (MODE == 0) {
            float4 r4 = *(const float4*)(ea + (size_t)grow * D + c);
            *(float4*)(out + (size_t)grow * D + c) =
                make_float4(r4.x + y0, r4.y + y1, r4.z + y2, r4.w + y3);
            long long dn = is64 ? e64[E + grow] : (long long)e32[E + grow];
            size_t dbase = (size_t)dn * D + c;
            atomicAdd(&g_agg[dbase + 0], y0);
            atomicAdd(&g_agg[dbase + 1], y1);
            atomicAdd(&g_agg[dbase + 2], y2);
            atomicAdd(&g_agg[dbase + 3], y3);
            if (lane == 0) atomicAdd(&g_cnt[dn], 1.0f);
        } else if (MODE == 1) {
            float4 r4 = *(const float4*)(rx + (size_t)grow * D + c);
            *(float4*)(out + (size_t)grow * D + c) =
                make_float4(r4.x + y0, r4.y + y1, r4.z + y2, r4.w + y3);
        } else {
            float4 r4 = *(const float4*)(sx + (size_t)grow * D + c);
            *(float4*)(out + (size_t)grow * D + c) =
                make_float4(r4.x + y0, r4.y + y1, r4.z + y2, r4.w + y3);
        }
    }
}

extern "C" void kernel_launch(void* const* d_in, const int* in_sizes, int n_in,
                              void* d_out, int out_size)
{
    const float*     sx   = (const float*)d_in[0];
    const float*     rx   = (const float*)d_in[1];
    const float*     ea   = (const float*)d_in[2];
    const int*       e32  = (const int*)d_in[3];
    const long long* e64  = (const long long*)d_in[3];
    const float *ew1 = (const float*)d_in[4],  *eb1 = (const float*)d_in[5];
    const float *ew2 = (const float*)d_in[6],  *eb2 = (const float*)d_in[7];
    const float *eg  = (const float*)d_in[8],  *ebt = (const float*)d_in[9];
    const float *nw1 = (const float*)d_in[10], *nb1 = (const float*)d_in[11];
    const float *nw2 = (const float*)d_in[12], *nb2 = (const float*)d_in[13];
    const float *ng  = (const float*)d_in[14], *nbt = (const float*)d_in[15];
    const float *sw1 = (const float*)d_in[16], *sb1 = (const float*)d_in[17];
    const float *sw2 = (const float*)d_in[18], *sb2 = (const float*)d_in[19];
    const float *sg  = (const float*)d_in[20], *sbt = (const float*)d_in[21];

    const int N = in_sizes[0] / D;
    const int E = in_sizes[3] / 2;

    float* out          = (float*)d_out;
    float* sender_out   = out;
    float* receiver_out = out + (size_t)N * D;
    float* edge_out     = out + (size_t)2 * N * D;

    cudaFuncSetAttribute(mlp_kernel<3 * D, 0>, cudaFuncAttributeMaxDynamicSharedMemorySize, SMEM_BYTES);
    cudaFuncSetAttribute(mlp_kernel<2 * D, 1>, cudaFuncAttributeMaxDynamicSharedMemorySize, SMEM_BYTES);
    cudaFuncSetAttribute(mlp_kernel<D, 2>,     cudaFuncAttributeMaxDynamicSharedMemorySize, SMEM_BYTES);

    prep_kernel<<<(384 * 256 + 255) / 256, 256>>>(ew1, OFF_W1E, 384, 256);
    prep_kernel<<<(256 * 256 + 255) / 256, 256>>>(nw1, OFF_W1N, 256, 256);
    prep_kernel<<<(128 * 256 + 255) / 256, 256>>>(sw1, OFF_W1S, 128, 256);
    prep_kernel<<<(256 * 128 + 255) / 256, 256>>>(ew2, OFF_W2E, 256, 128);
    prep_kernel<<<(256 * 128 + 255) / 256, 256>>>(nw2, OFF_W2N, 256, 128);
    prep_kernel<<<(256 * 128 + 255) / 256, 256>>>(sw2, OFF_W2S, 256, 128);

    probe_kernel<<<1, 32>>>(e32);
    zero_kernel<<<(N * (D + 1) + 255) / 256, 256>>>(N);

    mlp_kernel<3 * D, 0><<<(E + 63) / 64, 512, SMEM_BYTES>>>(
        sx, rx, ea, e32, e64, eb1, eb2, eg, ebt, OFF_W1E, OFF_W2E, edge_out, E, E);

    mlp_kernel<2 * D, 1><<<(N + 63) / 64, 512, SMEM_BYTES>>>(
        sx, rx, ea, e32, e64, nb1, nb2, ng, nbt, OFF_W1N, OFF_W2N, receiver_out, N, E);

    mlp_kernel<D, 2><<<(N + 63) / 64, 512, SMEM_BYTES>>>(
        sx, rx, ea, e32, e64, sb1, sb2, sg, sbt, OFF_W1S, OFF_W2S, sender_out, N, E);
}

// round 14
// speedup vs baseline: 2.0815x; 1.1945x over previous
#include <cuda_runtime.h>
#include <cuda_bf16.h>
#include <cstdint>

#define D 128
#define H 256
#define MAXN 40000
#define LN_EPS 1e-5f

__device__ float g_agg[MAXN * D];
__device__ float g_cnt[MAXN];
__device__ int g_idx64;

#define OFF_W1E 0
#define OFF_W1N 98304
#define OFF_W1S 163840
#define OFF_W2E 196608
#define OFF_W2N 229376
#define OFF_W2S 262144
#define WTOT    294912
__device__ __nv_bfloat16 g_whi[WTOT];
__device__ __nv_bfloat16 g_wlo[WTOT];

__device__ __forceinline__ float silu_f(float x) { return x / (1.0f + __expf(-x)); }

__device__ __forceinline__ void prep_one(const float* src, int dstoff, int K, int N, int d) {
    int n = d / K, k = d - n * K;
    float x = src[(size_t)k * N + n];
    __nv_bfloat16 h = __float2bfloat16(x);
    g_whi[dstoff + d] = h;
    g_wlo[dstoff + d] = __float2bfloat16(x - __bfloat162float(h));
}
// Two matrices per launch (keeps total pre-launch count at 5 so ncu -s 5 hits the edge kernel)
__global__ void prep2_kernel(const float* s1, int o1, int K1, int N1,
                             const float* s2, int o2, int K2, int N2) {
    int d = blockIdx.x * blockDim.x + threadIdx.x;
    int t1 = K1 * N1;
    if (d < t1) prep_one(s1, o1, K1, N1, d);
    else {
        d -= t1;
        if (d < K2 * N2) prep_one(s2, o2, K2, N2, d);
    }
}

__global__ void probe_kernel(const int* __restrict__ e32) {
    if (blockIdx.x == 0 && threadIdx.x == 0) {
        int all0 = 1;
#pragma unroll 1
        for (int i = 0; i < 64; ++i)
            if (e32[2 * i + 1] != 0) { all0 = 0; break; }
        g_idx64 = all0;
    }
}

__global__ void zero_kernel(int N) {
    int i = blockIdx.x * blockDim.x + threadIdx.x;
    if (i < N * D) g_agg[i] = 0.0f;
    if (i < N)     g_cnt[i] = 0.0f;
}

__device__ __forceinline__ uint32_t pack_bf16x2(float lo, float hi) {
    uint32_t r;
    asm("cvt.rn.bf16x2.f32 %0, %1, %2;" : "=r"(r) : "f"(hi), "f"(lo));
    return r;
}
__device__ __forceinline__ void split2(float2 f, uint32_t& h, uint32_t& l) {
    h = pack_bf16x2(f.x, f.y);
    float hx = __uint_as_float(h << 16);
    float hy = __uint_as_float(h & 0xffff0000u);
    l = pack_bf16x2(f.x - hx, f.y - hy);
}
__device__ __forceinline__ void mma_bf16(float c[4],
                                         const uint32_t a[4], uint32_t b0, uint32_t b1) {
    asm volatile(
        "mma.sync.aligned.m16n8k16.row.col.f32.bf16.bf16.f32 "
        "{%0,%1,%2,%3},{%4,%5,%6,%7},{%8,%9},{%0,%1,%2,%3};"
        : "+f"(c[0]), "+f"(c[1]), "+f"(c[2]), "+f"(c[3])
        : "r"(a[0]), "r"(a[1]), "r"(a[2]), "r"(a[3]), "r"(b0), "r"(b1));
}
#define LDSM_X4(r_, addr) \
    asm volatile("ldmatrix.sync.aligned.m8n8.x4.shared.b16 {%0,%1,%2,%3}, [%4];" \
        : "=r"((r_)[0]), "=r"((r_)[1]), "=r"((r_)[2]), "=r"((r_)[3]) : "r"(addr))
#define CP16(dst, src) \
    asm volatile("cp.async.ca.shared.global [%0], [%1], 16;" :: "r"(dst), "l"(src))
#define CP_COMMIT() asm volatile("cp.async.commit_group;")
#define CP_WAIT0()  asm volatile("cp.async.wait_group 0;" ::: "memory")
#define CP_WAIT1()  asm volatile("cp.async.wait_group 1;" ::: "memory")

// smem (128 rows/CTA, phase-overlapped):
//  B1 double buf  [0, 81920)        (GEMM1; buf stride 40960, lo plane +20480)
//  B2 double buf  [0, 40960)        (GEMM2; buf stride 20480, lo plane +10240)
//  A planes       [81920, 102400)   (hi 10240, lo +10240; dead after GEMM1)
//  H planes       [40960, 176128)   (hi stride-528 67584, lo +67584; written post-GEMM1)
//  Cs fp32        [40960, 108544)   (post-GEMM2, stride 132 floats)
//  b1s            [176128, 177152)  b2s [177152, 177664)
#define SM_B1  0
#define SM_B2  0
#define SM_A   81920
#define SM_H   40960
#define SM_CS  40960
#define SM_B1S 176128
#define SM_B2S 177152
#define SMEM_BYTES 177664
#define CS_STRIDE 132

// mma.sync bf16 3-product fused MLP+LN. 512 threads / 16 warps.
// 128 rows/CTA; warp grid 4 row-groups (32 rows) x 4 col-groups (64 / 32 cols).
template <int KTOT, int MODE>
__global__ void __launch_bounds__(512, 1) mlp_kernel(
    const float* __restrict__ sx, const float* __restrict__ rx,
    const float* __restrict__ ea,
    const int* e32, const long long* e64,
    const float* __restrict__ b1, const float* __restrict__ b2,
    const float* __restrict__ gm, const float* __restrict__ bt,
    int w1off, int w2off, float* __restrict__ out, int M, int E)
{
    extern __shared__ char smem[];
    const uint32_t sbase = (uint32_t)__cvta_generic_to_shared(smem);
    float* b1s = (float*)(smem + SM_B1S);
    float* b2s = (float*)(smem + SM_B2S);

    const int tid  = threadIdx.x;
    const int lane = tid & 31;
    const int warp = tid >> 5;
    const int row0 = blockIdx.x * 128;
    const int is64 = (MODE == 0) ? g_idx64 : 0;

    const int r0 = (warp & 3) * 32;
    const int n0 = (warp >> 2) * 64;
    const int m0 = (warp >> 2) * 32;
    const int g   = lane >> 2;
    const int tig = lane & 3;

    if (tid < 256) b1s[tid] = b1[tid];
    else if (tid < 384) b2s[tid - 256] = b2[tid - 256];

    const int aRow = (lane & 7) + ((lane >> 3) & 1) * 8;
    const int aK8  = ((lane >> 4) & 1) * 8;
    const int bN   = (lane & 7) + ((lane >> 4) & 1) * 8;
    const int bK8  = ((lane >> 3) & 1) * 8;
    const uint32_t addrA  = sbase + SM_A + (r0 + aRow) * 80 + aK8 * 2;
    const uint32_t addrH  = sbase + SM_H + (r0 + aRow) * 528 + aK8 * 2;
    const uint32_t addrB1 = sbase + SM_B1 + (n0 + bN) * 80 + bK8 * 2;
    const uint32_t addrB2 = sbase + SM_B2 + (m0 + bN) * 80 + bK8 * 2;

    auto stageB1 = [&](int kt, int bsel) {
        const int ktb = kt * 32;
        const uint32_t db = sbase + SM_B1 + bsel * 40960;
#pragma unroll
        for (int i = 0; i < 2; i++) {
            int idx = tid + i * 512;
            int n = idx >> 2, q = idx & 3;
            uint32_t dst = db + n * 80 + q * 16;
            CP16(dst,         (const char*)(g_whi + w1off + (size_t)n * KTOT + ktb) + q * 16);
            CP16(dst + 20480, (const char*)(g_wlo + w1off + (size_t)n * KTOT + ktb) + q * 16);
        }
    };
    auto stageB2 = [&](int kt, int bsel) {
        const int ktb = kt * 32;
        const uint32_t db = sbase + SM_B2 + bsel * 20480;
        int n = tid >> 2, q = tid & 3;
        uint32_t dst = db + n * 80 + q * 16;
        CP16(dst,         (const char*)(g_whi + w2off + (size_t)n * H + ktb) + q * 16);
        CP16(dst + 10240, (const char*)(g_wlo + w2off + (size_t)n * H + ktb) + q * 16);
    };

    // Cache per-thread gather state for the 2 A-rows this thread stages.
    long long sidxA[2], didxA[2];
    float rcA[2];
    bool validA[2];
#pragma unroll
    for (int i = 0; i < 2; i++) {
        int row = row0 + (tid >> 3) + i * 64;
        validA[i] = (row < M);
        sidxA[i] = didxA[i] = 0; rcA[i] = 1.0f;
        if (validA[i]) {
            if (MODE == 0) {
                sidxA[i] = is64 ? e64[row] : (long long)e32[row];
                didxA[i] = is64 ? e64[E + row] : (long long)e32[E + row];
            } else if (MODE == 1) {
                rcA[i] = 1.0f / fmaxf(g_cnt[row], 1.0f);
            }
        }
    }

    float c1[16][4];
#pragma unroll
    for (int j = 0; j < 16; j++)
#pragma unroll
        for (int q = 0; q < 4; q++) c1[j][q] = 0.0f;

    // ================= GEMM1: C1[128,256] =================
    const int NT1 = KTOT / 32;
    stageB1(0, 0);
    CP_COMMIT();

    for (int kt = 0; kt < NT1; ++kt) {
        const int ktb = kt * 32;
        // stage A tile (128 rows x 32 k): 2 rows per thread
#pragma unroll
        for (int i = 0; i < 2; i++) {
            int r  = (tid >> 3) + i * 64;
            int kl = (tid & 7) * 4;
            int kg = ktb + kl;
            float4 v = make_float4(0.f, 0.f, 0.f, 0.f);
            if (validA[i]) {
                const float* p;
                if (MODE == 0) {
                    if (kg < 128)       p = sx + (size_t)sidxA[i] * D + kg;
                    else if (kg < 256)  p = rx + (size_t)didxA[i] * D + (kg - 128);
                    else                p = ea + (size_t)(row0 + r) * D + (kg - 256);
                    v = *(const float4*)p;
                } else if (MODE == 1) {
                    if (kg < 128) {
                        v = *(const float4*)(rx + (size_t)(row0 + r) * D + kg);
                    } else {
                        float4 t = *(const float4*)(g_agg + (size_t)(row0 + r) * D + (kg - 128));
                        v.x = t.x * rcA[i]; v.y = t.y * rcA[i];
                        v.z = t.z * rcA[i]; v.w = t.w * rcA[i];
                    }
                } else {
                    v = *(const float4*)(sx + (size_t)(row0 + r) * D + kg);
                }
            }
            uint32_t h0, h1, l0, l1;
            split2(make_float2(v.x, v.y), h0, l0);
            split2(make_float2(v.z, v.w), h1, l1);
            *(uint2*)(smem + SM_A + r * 80 + kl * 2)         = make_uint2(h0, h1);
            *(uint2*)(smem + SM_A + 10240 + r * 80 + kl * 2) = make_uint2(l0, l1);
        }
        if (kt + 1 < NT1) { stageB1(kt + 1, (kt + 1) & 1); CP_COMMIT(); CP_WAIT1(); }
        else              { CP_WAIT0(); }
        __syncthreads();

        const uint32_t bb = addrB1 + (kt & 1) * 40960;
#pragma unroll
        for (int kc = 0; kc < 2; ++kc) {
            const int kb2 = kc * 32;
            uint32_t ah0[4], ah1[4], al0[4], al1[4];
            LDSM_X4(ah0, addrA + kb2);
            LDSM_X4(ah1, addrA + 1280 + kb2);
            LDSM_X4(al0, addrA + 10240 + kb2);
            LDSM_X4(al1, addrA + 11520 + kb2);
#pragma unroll
            for (int jj = 0; jj < 4; ++jj) {
                uint32_t ba = bb + jj * 1280 + kb2;
                uint32_t bh[4], bl[4];
                LDSM_X4(bh, ba);
                LDSM_X4(bl, ba + 20480);
                mma_bf16(c1[2 * jj],     ah0, bh[0], bh[1]);
                mma_bf16(c1[2 * jj],     ah0, bl[0], bl[1]);
                mma_bf16(c1[2 * jj],     al0, bh[0], bh[1]);
                mma_bf16(c1[2 * jj + 1], ah0, bh[2], bh[3]);
                mma_bf16(c1[2 * jj + 1], ah0, bl[2], bl[3]);
                mma_bf16(c1[2 * jj + 1], al0, bh[2], bh[3]);
                mma_bf16(c1[8 + 2 * jj],     ah1, bh[0], bh[1]);
                mma_bf16(c1[8 + 2 * jj],     ah1, bl[0], bl[1]);
                mma_bf16(c1[8 + 2 * jj],     al1, bh[0], bh[1]);
                mma_bf16(c1[8 + 2 * jj + 1], ah1, bh[2], bh[3]);
                mma_bf16(c1[8 + 2 * jj + 1], ah1, bl[2], bl[3]);
                mma_bf16(c1[8 + 2 * jj + 1], al1, bh[2], bh[3]);
            }
        }
        __syncthreads();
    }

    stageB2(0, 0);
    CP_COMMIT();

    // ---- bias + SiLU -> H hi/lo (stride 528) ----
#pragma unroll
    for (int rh = 0; rh < 2; rh++) {
#pragma unroll
        for (int jc = 0; jc < 8; jc++) {
            int col = n0 + jc * 8 + tig * 2;
            const float* cc = c1[rh * 8 + jc];
            float x0 = silu_f(cc[0] + b1s[col]);
            float x1 = silu_f(cc[1] + b1s[col + 1]);
            float x2 = silu_f(cc[2] + b1s[col]);
            float x3 = silu_f(cc[3] + b1s[col + 1]);
            int rowA = r0 + rh * 16 + g;
            uint32_t h, l;
            split2(make_float2(x0, x1), h, l);
            *(uint32_t*)(smem + SM_H + rowA * 528 + col * 2) = h;
            *(uint32_t*)(smem + SM_H + 67584 + rowA * 528 + col * 2) = l;
            split2(make_float2(x2, x3), h, l);
            *(uint32_t*)(smem + SM_H + (rowA + 8) * 528 + col * 2) = h;
            *(uint32_t*)(smem + SM_H + 67584 + (rowA + 8) * 528 + col * 2) = l;
        }
    }

    // ================= GEMM2: C2[128,128] =================
    float c2[8][4];
#pragma unroll
    for (int j = 0; j < 8; j++)
#pragma unroll
        for (int q = 0; q < 4; q++) c2[j][q] = 0.0f;

    const int NT2 = H / 32;
    for (int kt = 0; kt < NT2; ++kt) {
        if (kt + 1 < NT2) { stageB2(kt + 1, (kt + 1) & 1); CP_COMMIT(); CP_WAIT1(); }
        else              { CP_WAIT0(); }
        __syncthreads();   // also orders H writes before reads on first iter

        const uint32_t bb = addrB2 + (kt & 1) * 20480;
        const int ktb2 = kt * 64;
#pragma unroll
        for (int kc = 0; kc < 2; ++kc) {
            const int kb2 = kc * 32;
            uint32_t hh0[4], hh1[4], hl0[4], hl1[4];
            LDSM_X4(hh0, addrH + ktb2 + kb2);
            LDSM_X4(hh1, addrH + 8448 + ktb2 + kb2);
            LDSM_X4(hl0, addrH + 67584 + ktb2 + kb2);
            LDSM_X4(hl1, addrH + 76032 + ktb2 + kb2);
#pragma unroll
            for (int jj = 0; jj < 2; ++jj) {
                uint32_t ba = bb + jj * 1280 + kb2;
                uint32_t bh[4], bl[4];
                LDSM_X4(bh, ba);
                LDSM_X4(bl, ba + 10240);
                mma_bf16(c2[2 * jj],     hh0, bh[0], bh[1]);
                mma_bf16(c2[2 * jj],     hh0, bl[0], bl[1]);
                mma_bf16(c2[2 * jj],     hl0, bh[0], bh[1]);
                mma_bf16(c2[2 * jj + 1], hh0, bh[2], bh[3]);
                mma_bf16(c2[2 * jj + 1], hh0, bl[2], bl[3]);
                mma_bf16(c2[2 * jj + 1], hl0, bh[2], bh[3]);
                mma_bf16(c2[4 + 2 * jj],     hh1, bh[0], bh[1]);
                mma_bf16(c2[4 + 2 * jj],     hh1, bl[0], bl[1]);
                mma_bf16(c2[4 + 2 * jj],     hl1, bh[0], bh[1]);
                mma_bf16(c2[4 + 2 * jj + 1], hh1, bh[2], bh[3]);
                mma_bf16(c2[4 + 2 * jj + 1], hh1, bl[2], bl[3]);
                mma_bf16(c2[4 + 2 * jj + 1], hl1, bh[2], bh[3]);
            }
        }
        __syncthreads();
    }

    // ---- stage C2 -> Cs fp32 ----
    float* Cs = (float*)(smem + SM_CS);
#pragma unroll
    for (int rh = 0; rh < 2; rh++) {
#pragma unroll
        for (int jc = 0; jc < 4; jc++) {
            int col = m0 + jc * 8 + tig * 2;
            const float* cc = c2[rh * 4 + jc];
            int rowA = r0 + rh * 16 + g;
            *(float2*)(Cs + rowA * CS_STRIDE + col)       = make_float2(cc[0], cc[1]);
            *(float2*)(Cs + (rowA + 8) * CS_STRIDE + col) = make_float2(cc[2], cc[3]);
        }
    }
    __syncthreads();

    // ---- LN + residual + (edge) scatter: warp w rows w*8..+7 ----
    const int c = lane * 4;
#pragma unroll
    for (int i = 0; i < 8; i++) {
        int lrow = warp * 8 + i;
        int grow = row0 + lrow;
        if (grow >= M) continue;

        float4 vv = *(const float4*)(Cs + lrow * CS_STRIDE + c);
        float v0 = vv.x + b2s[c + 0];
        float v1 = vv.y + b2s[c + 1];
        float v2 = vv.z + b2s[c + 2];
        float v3 = vv.w + b2s[c + 3];

        float s  = v0 + v1 + v2 + v3;
        float sq = v0 * v0 + v1 * v1 + v2 * v2 + v3 * v3;
#pragma unroll
        for (int o = 16; o > 0; o >>= 1) {
            s  += __shfl_xor_sync(0xffffffffu, s,  o);
            sq += __shfl_xor_sync(0xffffffffu, sq, o);
        }
        float mean = s * (1.0f / 128.0f);
        float var  = sq * (1.0f / 128.0f) - mean * mean;
        float rs   = rsqrtf(var + LN_EPS);

        float y0 = (v0 - mean) * rs * gm[c + 0] + bt[c + 0];
        float y1 = (v1 - mean) * rs * gm[c + 1] + bt[c + 1];
        float y2 = (v2 - mean) * rs * gm[c + 2] + bt[c + 2];
        float y3 = (v3 - mean) * rs * gm[c + 3] + bt[c + 3];

        if (MODE == 0) {
            float4 r4 = *(const float4*)(ea + (size_t)grow * D + c);
            *(float4*)(out + (size_t)grow * D + c) =
                make_float4(r4.x + y0, r4.y + y1, r4.z + y2, r4.w + y3);
            long long dn = is64 ? e64[E + grow] : (long long)e32[E + grow];
            size_t dbase = (size_t)dn * D + c;
            atomicAdd(&g_agg[dbase + 0], y0);
            atomicAdd(&g_agg[dbase + 1], y1);
            atomicAdd(&g_agg[dbase + 2], y2);
            atomicAdd(&g_agg[dbase + 3], y3);
            if (lane == 0) atomicAdd(&g_cnt[dn], 1.0f);
        } else if (MODE == 1) {
            float4 r4 = *(const float4*)(rx + (size_t)grow * D + c);
            *(float4*)(out + (size_t)grow * D + c) =
                make_float4(r4.x + y0, r4.y + y1, r4.z + y2, r4.w + y3);
        } else {
            float4 r4 = *(const float4*)(sx + (size_t)grow * D + c);
            *(float4*)(out + (size_t)grow * D + c) =
                make_float4(r4.x + y0, r4.y + y1, r4.z + y2, r4.w + y3);
        }
    }
}

extern "C" void kernel_launch(void* const* d_in, const int* in_sizes, int n_in,
                              void* d_out, int out_size)
{
    const float*     sx   = (const float*)d_in[0];
    const float*     rx   = (const float*)d_in[1];
    const float*     ea   = (const float*)d_in[2];
    const int*       e32  = (const int*)d_in[3];
    const long long* e64  = (const long long*)d_in[3];
    const float *ew1 = (const float*)d_in[4],  *eb1 = (const float*)d_in[5];
    const float *ew2 = (const float*)d_in[6],  *eb2 = (const float*)d_in[7];
    const float *eg  = (const float*)d_in[8],  *ebt = (const float*)d_in[9];
    const float *nw1 = (const float*)d_in[10], *nb1 = (const float*)d_in[11];
    const float *nw2 = (const float*)d_in[12], *nb2 = (const float*)d_in[13];
    const float *ng  = (const float*)d_in[14], *nbt = (const float*)d_in[15];
    const float *sw1 = (const float*)d_in[16], *sb1 = (const float*)d_in[17];
    const float *sw2 = (const float*)d_in[18], *sb2 = (const float*)d_in[19];
    const float *sg  = (const float*)d_in[20], *sbt = (const float*)d_in[21];

    const int N = in_sizes[0] / D;
    const int E = in_sizes[3] / 2;

    float* out          = (float*)d_out;
    float* sender_out   = out;
    float* receiver_out = out + (size_t)N * D;
    float* edge_out     = out + (size_t)2 * N * D;

    cudaFuncSetAttribute(mlp_kernel<3 * D, 0>, cudaFuncAttributeMaxDynamicSharedMemorySize, SMEM_BYTES);
    cudaFuncSetAttribute(mlp_kernel<2 * D, 1>, cudaFuncAttributeMaxDynamicSharedMemorySize, SMEM_BYTES);
    cudaFuncSetAttribute(mlp_kernel<D, 2>,     cudaFuncAttributeMaxDynamicSharedMemorySize, SMEM_BYTES);

    // exactly 5 pre-launches -> ncu -s 5 profiles the edge kernel (launch #5)
    prep2_kernel<<<(98304 + 65536 + 255) / 256, 256>>>(ew1, OFF_W1E, 384, 256,
                                                       nw1, OFF_W1N, 256, 256);
    prep2_kernel<<<(32768 + 32768 + 255) / 256, 256>>>(sw1, OFF_W1S, 128, 256,
                                                       ew2, OFF_W2E, 256, 128);
    prep2_kernel<<<(32768 + 32768 + 255) / 256, 256>>>(nw2, OFF_W2N, 256, 128,
                                                       sw2, OFF_W2S, 256, 128);
    probe_kernel<<<1, 32>>>(e32);
    zero_kernel<<<(N * (D + 1) + 255) / 256, 256>>>(N);

    mlp_kernel<3 * D, 0><<<(E + 127) / 128, 512, SMEM_BYTES>>>(
        sx, rx, ea, e32, e64, eb1, eb2, eg, ebt, OFF_W1E, OFF_W2E, edge_out, E, E);

    mlp_kernel<2 * D, 1><<<(N + 127) / 128, 512, SMEM_BYTES>>>(
        sx, rx, ea, e32, e64, nb1, nb2, ng, nbt, OFF_W1N, OFF_W2N, receiver_out, N, E);

    mlp_kernel<D, 2><<<(N + 127) / 128, 512, SMEM_BYTES>>>(
        sx, rx, ea, e32, e64, sb1, sb2, sg, sbt, OFF_W1S, OFF_W2S, sender_out, N, E);
}

// round 15
// speedup vs baseline: 2.4146x; 1.1601x over previous
#include <cuda_runtime.h>
#include <cuda_bf16.h>
#include <cstdint>

#define D 128
#define H 256
#define MAXN 40000
#define LN_EPS 1e-5f

__device__ float g_agg[MAXN * D];
__device__ float g_cnt[MAXN];
__device__ int g_idx64;

#define OFF_W1E 0
#define OFF_W1N 98304
#define OFF_W1S 163840
#define OFF_W2E 196608
#define OFF_W2N 229376
#define OFF_W2S 262144
#define WTOT    294912
__device__ __nv_bfloat16 g_whi[WTOT];
__device__ __nv_bfloat16 g_wlo[WTOT];

__device__ __forceinline__ float silu_f(float x) { return x / (1.0f + __expf(-x)); }

__device__ __forceinline__ void prep_one(const float* src, int dstoff, int K, int N, int d) {
    int n = d / K, k = d - n * K;
    float x = src[(size_t)k * N + n];
    __nv_bfloat16 h = __float2bfloat16(x);
    g_whi[dstoff + d] = h;
    g_wlo[dstoff + d] = __float2bfloat16(x - __bfloat162float(h));
}
// All six weight matrices in ONE launch (keeps edge mlp_kernel as launch #4 for ncu)
__global__ void prep_all(const float* ew1, const float* nw1, const float* sw1,
                         const float* ew2, const float* nw2, const float* sw2) {
    int d = blockIdx.x * blockDim.x + threadIdx.x;
    if (d < 98304)       prep_one(ew1, OFF_W1E, 384, 256, d);
    else if (d < 163840) prep_one(nw1, OFF_W1N, 256, 256, d - 98304);
    else if (d < 196608) prep_one(sw1, OFF_W1S, 128, 256, d - 163840);
    else if (d < 229376) prep_one(ew2, OFF_W2E, 256, 128, d - 196608);
    else if (d < 262144) prep_one(nw2, OFF_W2N, 256, 128, d - 229376);
    else if (d < 294912) prep_one(sw2, OFF_W2S, 256, 128, d - 262144);
}

__global__ void probe_kernel(const int* __restrict__ e32) {
    if (blockIdx.x == 0 && threadIdx.x == 0) {
        int all0 = 1;
#pragma unroll 1
        for (int i = 0; i < 64; ++i)
            if (e32[2 * i + 1] != 0) { all0 = 0; break; }
        g_idx64 = all0;
    }
}

__global__ void zero_kernel(int N) {
    int i = blockIdx.x * blockDim.x + threadIdx.x;
    if (i < N * D) g_agg[i] = 0.0f;
    if (i < N)     g_cnt[i] = 0.0f;
}

__device__ __forceinline__ uint32_t pack_bf16x2(float lo, float hi) {
    uint32_t r;
    asm("cvt.rn.bf16x2.f32 %0, %1, %2;" : "=r"(r) : "f"(hi), "f"(lo));
    return r;
}
__device__ __forceinline__ void split2(float2 f, uint32_t& h, uint32_t& l) {
    h = pack_bf16x2(f.x, f.y);
    float hx = __uint_as_float(h << 16);
    float hy = __uint_as_float(h & 0xffff0000u);
    l = pack_bf16x2(f.x - hx, f.y - hy);
}
__device__ __forceinline__ void mma_bf16(float c[4],
                                         const uint32_t a[4], uint32_t b0, uint32_t b1) {
    asm volatile(
        "mma.sync.aligned.m16n8k16.row.col.f32.bf16.bf16.f32 "
        "{%0,%1,%2,%3},{%4,%5,%6,%7},{%8,%9},{%0,%1,%2,%3};"
        : "+f"(c[0]), "+f"(c[1]), "+f"(c[2]), "+f"(c[3])
        : "r"(a[0]), "r"(a[1]), "r"(a[2]), "r"(a[3]), "r"(b0), "r"(b1));
}
#define LDSM_X4(r_, addr) \
    asm volatile("ldmatrix.sync.aligned.m8n8.x4.shared.b16 {%0,%1,%2,%3}, [%4];" \
        : "=r"((r_)[0]), "=r"((r_)[1]), "=r"((r_)[2]), "=r"((r_)[3]) : "r"(addr))
#define CP16(dst, src) \
    asm volatile("cp.async.ca.shared.global [%0], [%1], 16;" :: "r"(dst), "l"(src))
#define CP_COMMIT() asm volatile("cp.async.commit_group;")
#define CP_WAIT0()  asm volatile("cp.async.wait_group 0;" ::: "memory")
#define CP_WAIT1()  asm volatile("cp.async.wait_group 1;" ::: "memory")

// smem (128 rows/CTA, phase-overlapped):
//  B1 double buf  [0, 81920)       B2 double buf [0, 40960)
//  A planes       [81920, 102400)  H planes [40960, 176128)
//  Cs fp32        [40960, 108544)  b1s [176128,177152) b2s [177152,177664)
#define SM_B1  0
#define SM_B2  0
#define SM_A   81920
#define SM_H   40960
#define SM_CS  40960
#define SM_B1S 176128
#define SM_B2S 177152
#define SMEM_BYTES 177664
#define CS_STRIDE 132

// mma.sync bf16 3-product fused MLP+LN. 512 threads / 16 warps, 128 rows/CTA.
// A-gather software-pipelined one tile ahead (loads fly under the MMA block).
template <int KTOT, int MODE>
__global__ void __launch_bounds__(512, 1) mlp_kernel(
    const float* __restrict__ sx, const float* __restrict__ rx,
    const float* __restrict__ ea,
    const int* e32, const long long* e64,
    const float* __restrict__ b1, const float* __restrict__ b2,
    const float* __restrict__ gm, const float* __restrict__ bt,
    int w1off, int w2off, float* __restrict__ out, int M, int E)
{
    extern __shared__ char smem[];
    const uint32_t sbase = (uint32_t)__cvta_generic_to_shared(smem);
    float* b1s = (float*)(smem + SM_B1S);
    float* b2s = (float*)(smem + SM_B2S);

    const int tid  = threadIdx.x;
    const int lane = tid & 31;
    const int warp = tid >> 5;
    const int row0 = blockIdx.x * 128;
    const int is64 = (MODE == 0) ? g_idx64 : 0;

    const int r0 = (warp & 3) * 32;
    const int n0 = (warp >> 2) * 64;
    const int m0 = (warp >> 2) * 32;
    const int g   = lane >> 2;
    const int tig = lane & 3;

    if (tid < 256) b1s[tid] = b1[tid];
    else if (tid < 384) b2s[tid - 256] = b2[tid - 256];

    const int aRow = (lane & 7) + ((lane >> 3) & 1) * 8;
    const int aK8  = ((lane >> 4) & 1) * 8;
    const int bN   = (lane & 7) + ((lane >> 4) & 1) * 8;
    const int bK8  = ((lane >> 3) & 1) * 8;
    const uint32_t addrA  = sbase + SM_A + (r0 + aRow) * 80 + aK8 * 2;
    const uint32_t addrH  = sbase + SM_H + (r0 + aRow) * 528 + aK8 * 2;
    const uint32_t addrB1 = sbase + SM_B1 + (n0 + bN) * 80 + bK8 * 2;
    const uint32_t addrB2 = sbase + SM_B2 + (m0 + bN) * 80 + bK8 * 2;

    auto stageB1 = [&](int kt, int bsel) {
        const int ktb = kt * 32;
        const uint32_t db = sbase + SM_B1 + bsel * 40960;
#pragma unroll
        for (int i = 0; i < 2; i++) {
            int idx = tid + i * 512;
            int n = idx >> 2, q = idx & 3;
            uint32_t dst = db + n * 80 + q * 16;
            CP16(dst,         (const char*)(g_whi + w1off + (size_t)n * KTOT + ktb) + q * 16);
            CP16(dst + 20480, (const char*)(g_wlo + w1off + (size_t)n * KTOT + ktb) + q * 16);
        }
    };
    auto stageB2 = [&](int kt, int bsel) {
        const int ktb = kt * 32;
        const uint32_t db = sbase + SM_B2 + bsel * 20480;
        int n = tid >> 2, q = tid & 3;
        uint32_t dst = db + n * 80 + q * 16;
        CP16(dst,         (const char*)(g_whi + w2off + (size_t)n * H + ktb) + q * 16);
        CP16(dst + 10240, (const char*)(g_wlo + w2off + (size_t)n * H + ktb) + q * 16);
    };

    // Per-thread gather state for the 2 A-rows this thread stages.
    long long sidxA[2], didxA[2];
    float rcA[2];
    bool validA[2];
#pragma unroll
    for (int i = 0; i < 2; i++) {
        int row = row0 + (tid >> 3) + i * 64;
        validA[i] = (row < M);
        sidxA[i] = didxA[i] = 0; rcA[i] = 1.0f;
        if (validA[i]) {
            if (MODE == 0) {
                sidxA[i] = is64 ? e64[row] : (long long)e32[row];
                didxA[i] = is64 ? e64[E + row] : (long long)e32[E + row];
            } else if (MODE == 1) {
                rcA[i] = 1.0f / fmaxf(g_cnt[row], 1.0f);
            }
        }
    }

    // A-gather for k-tile kt into registers (2 float4).
    auto loadA = [&](int kt, float4* v) {
#pragma unroll
        for (int i = 0; i < 2; i++) {
            int r  = (tid >> 3) + i * 64;
            int kl = (tid & 7) * 4;
            int kg = kt * 32 + kl;
            v[i] = make_float4(0.f, 0.f, 0.f, 0.f);
            if (validA[i]) {
                const float* p;
                if (MODE == 0) {
                    if (kg < 128)       p = sx + (size_t)sidxA[i] * D + kg;
                    else if (kg < 256)  p = rx + (size_t)didxA[i] * D + (kg - 128);
                    else                p = ea + (size_t)(row0 + r) * D + (kg - 256);
                    v[i] = *(const float4*)p;
                } else if (MODE == 1) {
                    if (kg < 128) {
                        v[i] = *(const float4*)(rx + (size_t)(row0 + r) * D + kg);
                    } else {
                        float4 t = *(const float4*)(g_agg + (size_t)(row0 + r) * D + (kg - 128));
                        v[i].x = t.x * rcA[i]; v[i].y = t.y * rcA[i];
                        v[i].z = t.z * rcA[i]; v[i].w = t.w * rcA[i];
                    }
                } else {
                    v[i] = *(const float4*)(sx + (size_t)(row0 + r) * D + kg);
                }
            }
        }
    };
    // split + store registers to the (single) A smem buffer
    auto storeA = [&](const float4* v) {
#pragma unroll
        for (int i = 0; i < 2; i++) {
            int r  = (tid >> 3) + i * 64;
            int kl = (tid & 7) * 4;
            uint32_t h0, h1, l0, l1;
            split2(make_float2(v[i].x, v[i].y), h0, l0);
            split2(make_float2(v[i].z, v[i].w), h1, l1);
            *(uint2*)(smem + SM_A + r * 80 + kl * 2)         = make_uint2(h0, h1);
            *(uint2*)(smem + SM_A + 10240 + r * 80 + kl * 2) = make_uint2(l0, l1);
        }
    };

    float c1[16][4];
#pragma unroll
    for (int j = 0; j < 16; j++)
#pragma unroll
        for (int q = 0; q < 4; q++) c1[j][q] = 0.0f;

    // ================= GEMM1: C1[128,256] =================
    const int NT1 = KTOT / 32;
    float4 vcur[2], vnxt[2];
    loadA(0, vcur);
    stageB1(0, 0);
    CP_COMMIT();

    for (int kt = 0; kt < NT1; ++kt) {
        storeA(vcur);   // regs for tile kt (loaded one iteration ago)
        if (kt + 1 < NT1) { stageB1(kt + 1, (kt + 1) & 1); CP_COMMIT(); CP_WAIT1(); }
        else              { CP_WAIT0(); }
        __syncthreads();

        if (kt + 1 < NT1) loadA(kt + 1, vnxt);   // flies under the MMA block

        const uint32_t bb = addrB1 + (kt & 1) * 40960;
#pragma unroll
        for (int kc = 0; kc < 2; ++kc) {
            const int kb2 = kc * 32;
            uint32_t ah0[4], ah1[4], al0[4], al1[4];
            LDSM_X4(ah0, addrA + kb2);
            LDSM_X4(ah1, addrA + 1280 + kb2);
            LDSM_X4(al0, addrA + 10240 + kb2);
            LDSM_X4(al1, addrA + 11520 + kb2);
#pragma unroll
            for (int jj = 0; jj < 4; ++jj) {
                uint32_t ba = bb + jj * 1280 + kb2;
                uint32_t bh[4], bl[4];
                LDSM_X4(bh, ba);
                LDSM_X4(bl, ba + 20480);
                mma_bf16(c1[2 * jj],     ah0, bh[0], bh[1]);
                mma_bf16(c1[2 * jj],     ah0, bl[0], bl[1]);
                mma_bf16(c1[2 * jj],     al0, bh[0], bh[1]);
                mma_bf16(c1[2 * jj + 1], ah0, bh[2], bh[3]);
                mma_bf16(c1[2 * jj + 1], ah0, bl[2], bl[3]);
                mma_bf16(c1[2 * jj + 1], al0, bh[2], bh[3]);
                mma_bf16(c1[8 + 2 * jj],     ah1, bh[0], bh[1]);
                mma_bf16(c1[8 + 2 * jj],     ah1, bl[0], bl[1]);
                mma_bf16(c1[8 + 2 * jj],     al1, bh[0], bh[1]);
                mma_bf16(c1[8 + 2 * jj + 1], ah1, bh[2], bh[3]);
                mma_bf16(c1[8 + 2 * jj + 1], ah1, bl[2], bl[3]);
                mma_bf16(c1[8 + 2 * jj + 1], al1, bh[2], bh[3]);
            }
        }
        __syncthreads();
        vcur[0] = vnxt[0]; vcur[1] = vnxt[1];
    }

    stageB2(0, 0);
    CP_COMMIT();

    // ---- bias + SiLU -> H hi/lo (stride 528) ----
#pragma unroll
    for (int rh = 0; rh < 2; rh++) {
#pragma unroll
        for (int jc = 0; jc < 8; jc++) {
            int col = n0 + jc * 8 + tig * 2;
            const float* cc = c1[rh * 8 + jc];
            float x0 = silu_f(cc[0] + b1s[col]);
            float x1 = silu_f(cc[1] + b1s[col + 1]);
            float x2 = silu_f(cc[2] + b1s[col]);
            float x3 = silu_f(cc[3] + b1s[col + 1]);
            int rowA = r0 + rh * 16 + g;
            uint32_t h, l;
            split2(make_float2(x0, x1), h, l);
            *(uint32_t*)(smem + SM_H + rowA * 528 + col * 2) = h;
            *(uint32_t*)(smem + SM_H + 67584 + rowA * 528 + col * 2) = l;
            split2(make_float2(x2, x3), h, l);
            *(uint32_t*)(smem + SM_H + (rowA + 8) * 528 + col * 2) = h;
            *(uint32_t*)(smem + SM_H + 67584 + (rowA + 8) * 528 + col * 2) = l;
        }
    }

    // ================= GEMM2: C2[128,128] =================
    float c2[8][4];
#pragma unroll
    for (int j = 0; j < 8; j++)
#pragma unroll
        for (int q = 0; q < 4; q++) c2[j][q] = 0.0f;

    const int NT2 = H / 32;
    for (int kt = 0; kt < NT2; ++kt) {
        if (kt + 1 < NT2) { stageB2(kt + 1, (kt + 1) & 1); CP_COMMIT(); CP_WAIT1(); }
        else              { CP_WAIT0(); }
        __syncthreads();

        const uint32_t bb = addrB2 + (kt & 1) * 20480;
        const int ktb2 = kt * 64;
#pragma unroll
        for (int kc = 0; kc < 2; ++kc) {
            const int kb2 = kc * 32;
            uint32_t hh0[4], hh1[4], hl0[4], hl1[4];
            LDSM_X4(hh0, addrH + ktb2 + kb2);
            LDSM_X4(hh1, addrH + 8448 + ktb2 + kb2);
            LDSM_X4(hl0, addrH + 67584 + ktb2 + kb2);
            LDSM_X4(hl1, addrH + 76032 + ktb2 + kb2);
#pragma unroll
            for (int jj = 0; jj < 2; ++jj) {
                uint32_t ba = bb + jj * 1280 + kb2;
                uint32_t bh[4], bl[4];
                LDSM_X4(bh, ba);
                LDSM_X4(bl, ba + 10240);
                mma_bf16(c2[2 * jj],     hh0, bh[0], bh[1]);
                mma_bf16(c2[2 * jj],     hh0, bl[0], bl[1]);
                mma_bf16(c2[2 * jj],     hl0, bh[0], bh[1]);
                mma_bf16(c2[2 * jj + 1], hh0, bh[2], bh[3]);
                mma_bf16(c2[2 * jj + 1], hh0, bl[2], bl[3]);
                mma_bf16(c2[2 * jj + 1], hl0, bh[2], bh[3]);
                mma_bf16(c2[4 + 2 * jj],     hh1, bh[0], bh[1]);
                mma_bf16(c2[4 + 2 * jj],     hh1, bl[0], bl[1]);
                mma_bf16(c2[4 + 2 * jj],     hl1, bh[0], bh[1]);
                mma_bf16(c2[4 + 2 * jj + 1], hh1, bh[2], bh[3]);
                mma_bf16(c2[4 + 2 * jj + 1], hh1, bl[2], bl[3]);
                mma_bf16(c2[4 + 2 * jj + 1], hl1, bh[2], bh[3]);
            }
        }
        __syncthreads();
    }

    // ---- stage C2 -> Cs fp32 ----
    float* Cs = (float*)(smem + SM_CS);
#pragma unroll
    for (int rh = 0; rh < 2; rh++) {
#pragma unroll
        for (int jc = 0; jc < 4; jc++) {
            int col = m0 + jc * 8 + tig * 2;
            const float* cc = c2[rh * 4 + jc];
            int rowA = r0 + rh * 16 + g;
            *(float2*)(Cs + rowA * CS_STRIDE + col)       = make_float2(cc[0], cc[1]);
            *(float2*)(Cs + (rowA + 8) * CS_STRIDE + col) = make_float2(cc[2], cc[3]);
        }
    }
    __syncthreads();

    // ---- LN + residual + (edge) scatter: warp w rows w*8..+7 ----
    const int c = lane * 4;
#pragma unroll
    for (int i = 0; i < 8; i++) {
        int lrow = warp * 8 + i;
        int grow = row0 + lrow;
        if (grow >= M) continue;

        float4 vv = *(const float4*)(Cs + lrow * CS_STRIDE + c);
        float v0 = vv.x + b2s[c + 0];
        float v1 = vv.y + b2s[c + 1];
        float v2 = vv.z + b2s[c + 2];
        float v3 = vv.w + b2s[c + 3];

        float s  = v0 + v1 + v2 + v3;
        float sq = v0 * v0 + v1 * v1 + v2 * v2 + v3 * v3;
#pragma unroll
        for (int o = 16; o > 0; o >>= 1) {
            s  += __shfl_xor_sync(0xffffffffu, s,  o);
            sq += __shfl_xor_sync(0xffffffffu, sq, o);
        }
        float mean = s * (1.0f / 128.0f);
        float var  = sq * (1.0f / 128.0f) - mean * mean;
        float rs   = rsqrtf(var + LN_EPS);

        float y0 = (v0 - mean) * rs * gm[c + 0] + bt[c + 0];
        float y1 = (v1 - mean) * rs * gm[c + 1] + bt[c + 1];
        float y2 = (v2 - mean) * rs * gm[c + 2] + bt[c + 2];
        float y3 = (v3 - mean) * rs * gm[c + 3] + bt[c + 3];

        if (MODE == 0) {
            float4 r4 = *(const float4*)(ea + (size_t)grow * D + c);
            *(float4*)(out + (size_t)grow * D + c) =
                make_float4(r4.x + y0, r4.y + y1, r4.z + y2, r4.w + y3);
            long long dn = is64 ? e64[E + grow] : (long long)e32[E + grow];
            size_t dbase = (size_t)dn * D + c;
            atomicAdd(&g_agg[dbase + 0], y0);
            atomicAdd(&g_agg[dbase + 1], y1);
            atomicAdd(&g_agg[dbase + 2], y2);
            atomicAdd(&g_agg[dbase + 3], y3);
            if (lane == 0) atomicAdd(&g_cnt[dn], 1.0f);
        } else if (MODE == 1) {
            float4 r4 = *(const float4*)(rx + (size_t)grow * D + c);
            *(float4*)(out + (size_t)grow * D + c) =
                make_float4(r4.x + y0, r4.y + y1, r4.z + y2, r4.w + y3);
        } else {
            float4 r4 = *(const float4*)(sx + (size_t)grow * D + c);
            *(float4*)(out + (size_t)grow * D + c) =
                make_float4(r4.x + y0, r4.y + y1, r4.z + y2, r4.w + y3);
        }
    }
}

extern "C" void kernel_launch(void* const* d_in, const int* in_sizes, int n_in,
                              void* d_out, int out_size)
{
    const float*     sx   = (const float*)d_in[0];
    const float*     rx   = (const float*)d_in[1];
    const float*     ea   = (const float*)d_in[2];
    const int*       e32  = (const int*)d_in[3];
    const long long* e64  = (const long long*)d_in[3];
    const float *ew1 = (const float*)d_in[4],  *eb1 = (const float*)d_in[5];
    const float *ew2 = (const float*)d_in[6],  *eb2 = (const float*)d_in[7];
    const float *eg  = (const float*)d_in[8],  *ebt = (const float*)d_in[9];
    const float *nw1 = (const float*)d_in[10], *nb1 = (const float*)d_in[11];
    const float *nw2 = (const float*)d_in[12], *nb2 = (const float*)d_in[13];
    const float *ng  = (const float*)d_in[14], *nbt = (const float*)d_in[15];
    const float *sw1 = (const float*)d_in[16], *sb1 = (const float*)d_in[17];
    const float *sw2 = (const float*)d_in[18], *sb2 = (const float*)d_in[19];
    const float *sg  = (const float*)d_in[20], *sbt = (const float*)d_in[21];

    const int N = in_sizes[0] / D;
    const int E = in_sizes[3] / 2;

    float* out          = (float*)d_out;
    float* sender_out   = out;
    float* receiver_out = out + (size_t)N * D;
    float* edge_out     = out + (size_t)2 * N * D;

    cudaFuncSetAttribute(mlp_kernel<3 * D, 0>, cudaFuncAttributeMaxDynamicSharedMemorySize, SMEM_BYTES);
    cudaFuncSetAttribute(mlp_kernel<2 * D, 1>, cudaFuncAttributeMaxDynamicSharedMemorySize, SMEM_BYTES);
    cudaFuncSetAttribute(mlp_kernel<D, 2>,     cudaFuncAttributeMaxDynamicSharedMemorySize, SMEM_BYTES);

    // launches: 1=prep_all, 2=probe, 3=zero, 4=EDGE (ncu target), 5=node, 6=sender
    prep_all<<<(WTOT + 255) / 256, 256>>>(ew1, nw1, sw1, ew2, nw2, sw2);
    probe_kernel<<<1, 32>>>(e32);
    zero_kernel<<<(N * (D + 1) + 255) / 256, 256>>>(N);

    mlp_kernel<3 * D, 0><<<(E + 127) / 128, 512, SMEM_BYTES>>>(
        sx, rx, ea, e32, e64, eb1, eb2, eg, ebt, OFF_W1E, OFF_W2E, edge_out, E, E);

    mlp_kernel<2 * D, 1><<<(N + 127) / 128, 512, SMEM_BYTES>>>(
        sx, rx, ea, e32, e64, nb1, nb2, ng, nbt, OFF_W1N, OFF_W2N, receiver_out, N, E);

    mlp_kernel<D, 2><<<(N + 127) / 128, 512, SMEM_BYTES>>>(
        sx, rx, ea, e32, e64, sb1, sb2, sg, sbt, OFF_W1S, OFF_W2S, sender_out, N, E);
}